// round 1
// baseline (speedup 1.0000x reference)
#include <cuda_runtime.h>
#include <math.h>

#define BB 16
#define TT 1024
#define DD 1024
#define HH 16
#define HDD 64

// Scratch (allocation-free rule: __device__ globals)
__device__ float g_qkv[BB * TT * 3 * DD];   // [B, T, 3D]
__device__ float g_attn[BB * TT * DD];      // [B, T, D]  (head-major within row == final layout)

// ---------------------------------------------------------------------------
// Generic tiled SGEMM with bias: C[M,N] = A[M,K] @ W[K,N] + bias[N]
// BM=BN=128, BK=16, 256 threads, 8x8 microtile per thread.
// Assumes M%128==0, N%128==0, K%16==0 (true for all our shapes).
// ---------------------------------------------------------------------------
__global__ void gemm_bias_kernel(const float* __restrict__ A,
                                 const float* __restrict__ W,
                                 const float* __restrict__ bias,
                                 float* __restrict__ C,
                                 int M, int N, int K)
{
    constexpr int BM = 128, BN = 128, BK = 16;
    __shared__ float As[BK][132];   // transposed A tile, padded
    __shared__ float Bs[BK][BN];

    const int tid = threadIdx.x;
    const int tx = tid & 15;
    const int ty = tid >> 4;
    const int blockRow = blockIdx.y * BM;
    const int blockCol = blockIdx.x * BN;

    float acc[8][8] = {};

    for (int kt = 0; kt < K; kt += BK) {
        // Load A tile [BM][BK] -> As transposed [BK][BM]
        #pragma unroll
        for (int l = 0; l < 2; l++) {
            int id = tid + l * 256;           // 0..511 float4 slots
            int r  = id >> 2;                 // 0..127
            int c4 = (id & 3) * 4;            // 0,4,8,12
            float4 v = *reinterpret_cast<const float4*>(
                &A[(size_t)(blockRow + r) * K + kt + c4]);
            As[c4 + 0][r] = v.x;
            As[c4 + 1][r] = v.y;
            As[c4 + 2][r] = v.z;
            As[c4 + 3][r] = v.w;
        }
        // Load W tile [BK][BN]
        #pragma unroll
        for (int l = 0; l < 2; l++) {
            int id = tid + l * 256;           // 0..511 float4 slots
            int r  = id >> 5;                 // 0..15
            int c4 = (id & 31) * 4;           // 0..124
            float4 v = *reinterpret_cast<const float4*>(
                &W[(size_t)(kt + r) * N + blockCol + c4]);
            *reinterpret_cast<float4*>(&Bs[r][c4]) = v;
        }
        __syncthreads();

        #pragma unroll
        for (int k = 0; k < BK; k++) {
            float4 a0 = *reinterpret_cast<const float4*>(&As[k][ty * 8]);
            float4 a1 = *reinterpret_cast<const float4*>(&As[k][ty * 8 + 4]);
            float4 b0 = *reinterpret_cast<const float4*>(&Bs[k][tx * 8]);
            float4 b1 = *reinterpret_cast<const float4*>(&Bs[k][tx * 8 + 4]);
            float ra[8] = {a0.x, a0.y, a0.z, a0.w, a1.x, a1.y, a1.z, a1.w};
            float rb[8] = {b0.x, b0.y, b0.z, b0.w, b1.x, b1.y, b1.z, b1.w};
            #pragma unroll
            for (int i = 0; i < 8; i++)
                #pragma unroll
                for (int j = 0; j < 8; j++)
                    acc[i][j] += ra[i] * rb[j];
        }
        __syncthreads();
    }

    // Write back with bias
    #pragma unroll
    for (int i = 0; i < 8; i++) {
        int row = blockRow + ty * 8 + i;
        #pragma unroll
        for (int jq = 0; jq < 2; jq++) {
            int col = blockCol + tx * 8 + jq * 4;
            float4 v;
            v.x = acc[i][jq * 4 + 0] + bias[col + 0];
            v.y = acc[i][jq * 4 + 1] + bias[col + 1];
            v.z = acc[i][jq * 4 + 2] + bias[col + 2];
            v.w = acc[i][jq * 4 + 3] + bias[col + 3];
            *reinterpret_cast<float4*>(&C[(size_t)row * N + col]) = v;
        }
    }
}

// ---------------------------------------------------------------------------
// Flash-style attention: one block = 64 query rows of one (b, h).
// 256 threads, thread (tx,ty) owns S rows ty*4..+3, cols tx*4..+3,
// and O rows ty*4..+3, dims tx*4..+3.
// Dynamic smem: Qt[64][65] (transposed), Kt[64][65] (transposed, reused as P),
//               Vs[64][64].
// ---------------------------------------------------------------------------
__global__ void attn_kernel(const float* __restrict__ qkv,
                            float* __restrict__ out)
{
    extern __shared__ float sm[];
    float* Qt = sm;                 // [64][65], Qt[d*65 + i]
    float* Kt = sm + 64 * 65;       // [64][65], Kt[d*65 + j]; later P[j*65 + i]
    float* Vs = sm + 2 * 64 * 65;   // [64][64], Vs[j*64 + d]

    const int b  = blockIdx.z;
    const int h  = blockIdx.y;
    const int qt = blockIdx.x;
    const int tid = threadIdx.x;
    const int tx = tid & 15;
    const int ty = tid >> 4;
    const int i0 = ty * 4;          // S/O row base
    const int j0 = tx * 4;          // S col base
    const int d0 = tx * 4;          // O dim base
    const int t0 = qt * 64;
    const float scale = 0.125f;     // 1/sqrt(64)

    const float* qbase = qkv + (size_t)b * TT * 3 * DD + h * HDD;

    // Load Q tile transposed: Qt[d][i] = Q[t0+i][d]
    #pragma unroll
    for (int it = 0; it < 4; it++) {
        int lin = it * 256 + tid;          // 0..1023
        int r = lin >> 4;                  // 0..63
        int dbase = (lin & 15) * 4;        // 0..60
        float4 v = *reinterpret_cast<const float4*>(
            qbase + (size_t)(t0 + r) * 3 * DD + dbase);
        Qt[(dbase + 0) * 65 + r] = v.x;
        Qt[(dbase + 1) * 65 + r] = v.y;
        Qt[(dbase + 2) * 65 + r] = v.z;
        Qt[(dbase + 3) * 65 + r] = v.w;
    }

    float o[4][4] = {};
    float m[4], l[4];
    #pragma unroll
    for (int ii = 0; ii < 4; ii++) { m[ii] = -1e30f; l[ii] = 0.f; }

    for (int kt = 0; kt < TT / 64; kt++) {
        __syncthreads();   // previous iter's P/V consumed; Q visible on iter 0

        // Load K tile transposed + V tile
        #pragma unroll
        for (int it = 0; it < 4; it++) {
            int lin = it * 256 + tid;
            int r = lin >> 4;
            int dbase = (lin & 15) * 4;
            const float* krow = qbase + DD     + (size_t)(kt * 64 + r) * 3 * DD;
            const float* vrow = qbase + 2 * DD + (size_t)(kt * 64 + r) * 3 * DD;
            float4 kv = *reinterpret_cast<const float4*>(krow + dbase);
            Kt[(dbase + 0) * 65 + r] = kv.x;
            Kt[(dbase + 1) * 65 + r] = kv.y;
            Kt[(dbase + 2) * 65 + r] = kv.z;
            Kt[(dbase + 3) * 65 + r] = kv.w;
            float4 vv = *reinterpret_cast<const float4*>(vrow + dbase);
            *reinterpret_cast<float4*>(&Vs[r * 64 + dbase]) = vv;
        }
        __syncthreads();

        // S = Q @ K^T (4x4 register tile)
        float s[4][4] = {};
        #pragma unroll 4
        for (int d = 0; d < 64; d++) {
            float qr[4], kr[4];
            #pragma unroll
            for (int ii = 0; ii < 4; ii++) qr[ii] = Qt[d * 65 + i0 + ii];
            #pragma unroll
            for (int jj = 0; jj < 4; jj++) kr[jj] = Kt[d * 65 + j0 + jj];
            #pragma unroll
            for (int ii = 0; ii < 4; ii++)
                #pragma unroll
                for (int jj = 0; jj < 4; jj++)
                    s[ii][jj] += qr[ii] * kr[jj];
        }

        // Online softmax update (row stats reduced over the 16-lane tx group)
        #pragma unroll
        for (int ii = 0; ii < 4; ii++) {
            float rmax = -1e30f;
            #pragma unroll
            for (int jj = 0; jj < 4; jj++) {
                s[ii][jj] *= scale;
                rmax = fmaxf(rmax, s[ii][jj]);
            }
            #pragma unroll
            for (int off = 8; off >= 1; off >>= 1)
                rmax = fmaxf(rmax, __shfl_xor_sync(0xffffffffu, rmax, off));
            float mn = fmaxf(m[ii], rmax);
            float a  = __expf(m[ii] - mn);
            m[ii] = mn;
            float rsum = 0.f;
            #pragma unroll
            for (int jj = 0; jj < 4; jj++) {
                float pv = __expf(s[ii][jj] - mn);
                s[ii][jj] = pv;
                rsum += pv;
            }
            #pragma unroll
            for (int off = 8; off >= 1; off >>= 1)
                rsum += __shfl_xor_sync(0xffffffffu, rsum, off);
            l[ii] = l[ii] * a + rsum;
            #pragma unroll
            for (int dd = 0; dd < 4; dd++) o[ii][dd] *= a;
        }

        __syncthreads();   // all S reads of Kt done before overwrite with P
        // Store P transposed into Kt: P[j][i]
        #pragma unroll
        for (int jj = 0; jj < 4; jj++)
            #pragma unroll
            for (int ii = 0; ii < 4; ii++)
                Kt[(j0 + jj) * 65 + i0 + ii] = s[ii][jj];
        __syncthreads();

        // O += P @ V
        #pragma unroll 4
        for (int j = 0; j < 64; j++) {
            float pr[4], vr[4];
            #pragma unroll
            for (int ii = 0; ii < 4; ii++) pr[ii] = Kt[j * 65 + i0 + ii];
            #pragma unroll
            for (int dd = 0; dd < 4; dd++) vr[dd] = Vs[j * 64 + d0 + dd];
            #pragma unroll
            for (int ii = 0; ii < 4; ii++)
                #pragma unroll
                for (int dd = 0; dd < 4; dd++)
                    o[ii][dd] += pr[ii] * vr[dd];
        }
    }

    // Normalize and write: out[b, t0+i, h*64 + d]  (== [B,T,C] final layout)
    #pragma unroll
    for (int ii = 0; ii < 4; ii++) {
        float inv = 1.f / l[ii];
        float4 v;
        v.x = o[ii][0] * inv;
        v.y = o[ii][1] * inv;
        v.z = o[ii][2] * inv;
        v.w = o[ii][3] * inv;
        *reinterpret_cast<float4*>(
            &out[(size_t)(b * TT + t0 + i0 + ii) * DD + h * HDD + d0]) = v;
    }
}

// ---------------------------------------------------------------------------
extern "C" void kernel_launch(void* const* d_in, const int* in_sizes, int n_in,
                              void* d_out, int out_size)
{
    const float* x     = (const float*)d_in[0];
    const float* w_qkv = (const float*)d_in[1];
    const float* b_qkv = (const float*)d_in[2];
    const float* w_out = (const float*)d_in[3];
    const float* b_out = (const float*)d_in[4];
    float* out = (float*)d_out;

    float* qkv;  cudaGetSymbolAddress((void**)&qkv,  g_qkv);
    float* attn; cudaGetSymbolAddress((void**)&attn, g_attn);

    const int ATTN_SMEM = (2 * 64 * 65 + 64 * 64) * (int)sizeof(float); // 49664 B
    cudaFuncSetAttribute(attn_kernel,
                         cudaFuncAttributeMaxDynamicSharedMemorySize, ATTN_SMEM);

    // 1) QKV projection: [16384,1024] @ [1024,3072] + b
    dim3 g1(3 * DD / 128, BB * TT / 128);
    gemm_bias_kernel<<<g1, 256>>>(x, w_qkv, b_qkv, qkv, BB * TT, 3 * DD, DD);

    // 2) Attention
    dim3 ga(TT / 64, HH, BB);
    attn_kernel<<<ga, 256, ATTN_SMEM>>>(qkv, attn);

    // 3) Output projection: [16384,1024] @ [1024,1024] + b
    dim3 g3(DD / 128, BB * TT / 128);
    gemm_bias_kernel<<<g3, 256>>>(attn, w_out, b_out, out, BB * TT, DD, DD);
}

// round 2
// speedup vs baseline: 1.1084x; 1.1084x over previous
#include <cuda_runtime.h>
#include <math.h>

#define BB 16
#define TT 1024
#define DD 1024
#define HH 16
#define HDD 64

// Scratch (allocation-free rule: __device__ globals)
__device__ float g_qkv[BB * TT * 3 * DD];   // [B, T, 3D]
__device__ float g_attn[BB * TT * DD];      // [B, T, D]

// ---------------------------------------------------------------------------
// tf32 helpers
// ---------------------------------------------------------------------------
__device__ __forceinline__ unsigned f2tf(float x) {
    unsigned r;
    asm("cvt.rna.tf32.f32 %0, %1;" : "=r"(r) : "f"(x));
    return r;
}

// m16n8k8 tf32 MMA, fp32 accumulate
__device__ __forceinline__ void mma8(float* c,
                                     unsigned a0, unsigned a1, unsigned a2, unsigned a3,
                                     unsigned b0, unsigned b1) {
    asm volatile(
        "mma.sync.aligned.m16n8k8.row.col.f32.tf32.tf32.f32 "
        "{%0,%1,%2,%3}, {%4,%5,%6,%7}, {%8,%9}, {%0,%1,%2,%3};"
        : "+f"(c[0]), "+f"(c[1]), "+f"(c[2]), "+f"(c[3])
        : "r"(a0), "r"(a1), "r"(a2), "r"(a3), "r"(b0), "r"(b1));
}

// ---------------------------------------------------------------------------
// tf32x2-split tensor-core GEMM with bias: C[M,N] = A[M,K] @ W[K,N] + bias[N]
// BM=BN=128, BK=32, 256 threads = 8 warps (4 row x 2 col), warp tile 32x64.
// fp32 held in smem; hi/lo tf32 split done in registers at fragment load.
// ---------------------------------------------------------------------------
__global__ void __launch_bounds__(256, 2)
gemm_tc_kernel(const float* __restrict__ A,
               const float* __restrict__ W,
               const float* __restrict__ bias,
               float* __restrict__ C,
               int M, int N, int K)
{
    constexpr int BK = 32;
    constexpr int AST = 36;    // A smem stride ([row][k])
    constexpr int BST = 136;   // B smem stride ([k][n])
    __shared__ float As[128 * AST];
    __shared__ float Bs[BK * BST];

    const int tid = threadIdx.x;
    const int wid = tid >> 5;
    const int wr = wid & 3;          // warp row (4)
    const int wc = wid >> 2;         // warp col (2)
    const int lane = tid & 31;
    const int g = lane >> 2;         // group id (row within frag)
    const int t = lane & 3;          // thread-in-group
    const int blockRow = blockIdx.y * 128;
    const int blockCol = blockIdx.x * 128;

    float c[2][8][4];
    #pragma unroll
    for (int mf = 0; mf < 2; mf++)
        #pragma unroll
        for (int nf = 0; nf < 8; nf++)
            #pragma unroll
            for (int i = 0; i < 4; i++) c[mf][nf][i] = 0.f;

    // prefetch registers
    float4 pa[4], pb[4];

    auto prefetch = [&](int kt) {
        #pragma unroll
        for (int l = 0; l < 4; l++) {
            int s = tid + l * 256;              // A: 1024 float4 slots
            int r = s >> 3, c4 = (s & 7) * 4;
            pa[l] = *reinterpret_cast<const float4*>(
                &A[(size_t)(blockRow + r) * K + kt + c4]);
        }
        #pragma unroll
        for (int l = 0; l < 4; l++) {
            int s = tid + l * 256;              // B: 1024 float4 slots
            int r = s >> 5, c4 = (s & 31) * 4;
            pb[l] = *reinterpret_cast<const float4*>(
                &W[(size_t)(kt + r) * N + blockCol + c4]);
        }
    };

    prefetch(0);

    for (int kt = 0; kt < K; kt += BK) {
        __syncthreads();
        // store tiles
        #pragma unroll
        for (int l = 0; l < 4; l++) {
            int s = tid + l * 256;
            int r = s >> 3, c4 = (s & 7) * 4;
            As[r * AST + c4 + 0] = pa[l].x;
            As[r * AST + c4 + 1] = pa[l].y;
            As[r * AST + c4 + 2] = pa[l].z;
            As[r * AST + c4 + 3] = pa[l].w;
        }
        #pragma unroll
        for (int l = 0; l < 4; l++) {
            int s = tid + l * 256;
            int r = s >> 5, c4 = (s & 31) * 4;
            Bs[r * BST + c4 + 0] = pb[l].x;
            Bs[r * BST + c4 + 1] = pb[l].y;
            Bs[r * BST + c4 + 2] = pb[l].z;
            Bs[r * BST + c4 + 3] = pb[l].w;
        }
        __syncthreads();

        if (kt + BK < K) prefetch(kt + BK);

        #pragma unroll
        for (int ks = 0; ks < 4; ks++) {
            // A fragments (fp32 -> hi/lo tf32 split)
            unsigned ah[2][4], al[2][4];
            #pragma unroll
            for (int mf = 0; mf < 2; mf++) {
                int r0 = wr * 32 + mf * 16 + g;
                float f[4];
                f[0] = As[r0 * AST + ks * 8 + t];
                f[1] = As[(r0 + 8) * AST + ks * 8 + t];
                f[2] = As[r0 * AST + ks * 8 + t + 4];
                f[3] = As[(r0 + 8) * AST + ks * 8 + t + 4];
                #pragma unroll
                for (int i = 0; i < 4; i++) {
                    unsigned h = f2tf(f[i]);
                    ah[mf][i] = h;
                    al[mf][i] = f2tf(f[i] - __uint_as_float(h));
                }
            }
            #pragma unroll
            for (int nf = 0; nf < 8; nf++) {
                int n = wc * 64 + nf * 8 + g;
                float b0f = Bs[(ks * 8 + t) * BST + n];
                float b1f = Bs[(ks * 8 + t + 4) * BST + n];
                unsigned bh0 = f2tf(b0f);
                unsigned bl0 = f2tf(b0f - __uint_as_float(bh0));
                unsigned bh1 = f2tf(b1f);
                unsigned bl1 = f2tf(b1f - __uint_as_float(bh1));
                #pragma unroll
                for (int mf = 0; mf < 2; mf++) {
                    mma8(c[mf][nf], ah[mf][0], ah[mf][1], ah[mf][2], ah[mf][3], bh0, bh1);
                    mma8(c[mf][nf], ah[mf][0], ah[mf][1], ah[mf][2], ah[mf][3], bl0, bl1);
                    mma8(c[mf][nf], al[mf][0], al[mf][1], al[mf][2], al[mf][3], bh0, bh1);
                }
            }
        }
    }

    // Writeback with bias
    #pragma unroll
    for (int mf = 0; mf < 2; mf++) {
        int row = blockRow + wr * 32 + mf * 16 + g;
        #pragma unroll
        for (int nf = 0; nf < 8; nf++) {
            int col = blockCol + wc * 64 + nf * 8 + 2 * t;
            float bx = bias[col], by = bias[col + 1];
            float2 v0 = make_float2(c[mf][nf][0] + bx, c[mf][nf][1] + by);
            float2 v1 = make_float2(c[mf][nf][2] + bx, c[mf][nf][3] + by);
            *reinterpret_cast<float2*>(&C[(size_t)row * N + col]) = v0;
            *reinterpret_cast<float2*>(&C[(size_t)(row + 8) * N + col]) = v1;
        }
    }
}

// ---------------------------------------------------------------------------
// Flash attention, tf32 tensor cores. Block = 64 q rows of one (b,h).
// 128 threads = 4 warps, warp w owns q rows [16w, 16w+16).
// Smem (all stored as tf32-rounded fp32 bit patterns, stride 72):
//   Qs[64][72], Ks[64][72] (reused as Ps), Vs[64][72]
// ---------------------------------------------------------------------------
__global__ void __launch_bounds__(128, 4)
attn_tc_kernel(const float* __restrict__ qkv, float* __restrict__ out)
{
    constexpr int ST = 72;
    extern __shared__ float sm[];
    float* Qs = sm;                  // [64][72]
    float* Ks = sm + 64 * ST;        // [64][72]; reused as Ps
    float* Vs = sm + 2 * 64 * ST;    // [64][72]
    float* Ps = Ks;

    const int b = blockIdx.z;
    const int h = blockIdx.y;
    const int qt = blockIdx.x;
    const int tid = threadIdx.x;
    const int w = tid >> 5;
    const int lane = tid & 31;
    const int g = lane >> 2;
    const int t = lane & 3;
    const int t0 = qt * 64;
    const float scale = 0.125f;      // folded into Q

    const float* qbase = qkv + (size_t)b * TT * 3 * DD + h * HDD;

    // Load Q tile (scaled, tf32-rounded)
    #pragma unroll
    for (int l = 0; l < 8; l++) {
        int s = tid + l * 128;               // 1024 float4 slots? no: 1024 slots of float4 = 64*16
        int r = s >> 4, c4 = (s & 15) * 4;
        float4 v = *reinterpret_cast<const float4*>(
            qbase + (size_t)(t0 + r) * 3 * DD + c4);
        Qs[r * ST + c4 + 0] = __uint_as_float(f2tf(v.x * scale));
        Qs[r * ST + c4 + 1] = __uint_as_float(f2tf(v.y * scale));
        Qs[r * ST + c4 + 2] = __uint_as_float(f2tf(v.z * scale));
        Qs[r * ST + c4 + 3] = __uint_as_float(f2tf(v.w * scale));
    }

    float o[8][4];
    #pragma unroll
    for (int nf = 0; nf < 8; nf++)
        #pragma unroll
        for (int i = 0; i < 4; i++) o[nf][i] = 0.f;
    float m[2] = {-1e30f, -1e30f};
    float l2s[2] = {0.f, 0.f};

    for (int kt = 0; kt < TT / 64; kt++) {
        __syncthreads();     // previous tile fully consumed
        // Load K, V tiles (tf32-rounded)
        #pragma unroll
        for (int ls = 0; ls < 8; ls++) {
            int s = tid + ls * 128;
            int r = s >> 4, c4 = (s & 15) * 4;
            const float* krow = qbase + DD + (size_t)(kt * 64 + r) * 3 * DD;
            const float* vrow = qbase + 2 * DD + (size_t)(kt * 64 + r) * 3 * DD;
            float4 kv = *reinterpret_cast<const float4*>(krow + c4);
            Ks[r * ST + c4 + 0] = __uint_as_float(f2tf(kv.x));
            Ks[r * ST + c4 + 1] = __uint_as_float(f2tf(kv.y));
            Ks[r * ST + c4 + 2] = __uint_as_float(f2tf(kv.z));
            Ks[r * ST + c4 + 3] = __uint_as_float(f2tf(kv.w));
            float4 vv = *reinterpret_cast<const float4*>(vrow + c4);
            Vs[r * ST + c4 + 0] = __uint_as_float(f2tf(vv.x));
            Vs[r * ST + c4 + 1] = __uint_as_float(f2tf(vv.y));
            Vs[r * ST + c4 + 2] = __uint_as_float(f2tf(vv.z));
            Vs[r * ST + c4 + 3] = __uint_as_float(f2tf(vv.w));
        }
        __syncthreads();

        // S = Q @ K^T  (16 rows x 64 cols per warp)
        float sc[8][4];
        #pragma unroll
        for (int nf = 0; nf < 8; nf++)
            #pragma unroll
            for (int i = 0; i < 4; i++) sc[nf][i] = 0.f;

        #pragma unroll
        for (int ks = 0; ks < 8; ks++) {
            int r0 = 16 * w + g;
            unsigned a0 = __float_as_uint(Qs[r0 * ST + ks * 8 + t]);
            unsigned a1 = __float_as_uint(Qs[(r0 + 8) * ST + ks * 8 + t]);
            unsigned a2 = __float_as_uint(Qs[r0 * ST + ks * 8 + t + 4]);
            unsigned a3 = __float_as_uint(Qs[(r0 + 8) * ST + ks * 8 + t + 4]);
            #pragma unroll
            for (int nf = 0; nf < 8; nf++) {
                unsigned b0 = __float_as_uint(Ks[(nf * 8 + g) * ST + ks * 8 + t]);
                unsigned b1 = __float_as_uint(Ks[(nf * 8 + g) * ST + ks * 8 + t + 4]);
                mma8(sc[nf], a0, a1, a2, a3, b0, b1);
            }
        }

        // Online softmax (rows g and g+8; c-layout: [0],[1] row g, [2],[3] row g+8)
        #pragma unroll
        for (int r = 0; r < 2; r++) {
            float mx = -1e30f;
            #pragma unroll
            for (int nf = 0; nf < 8; nf++)
                mx = fmaxf(mx, fmaxf(sc[nf][2 * r], sc[nf][2 * r + 1]));
            mx = fmaxf(mx, __shfl_xor_sync(0xffffffffu, mx, 1));
            mx = fmaxf(mx, __shfl_xor_sync(0xffffffffu, mx, 2));
            float mn = fmaxf(m[r], mx);
            float alpha = __expf(m[r] - mn);
            m[r] = mn;
            float sum = 0.f;
            #pragma unroll
            for (int nf = 0; nf < 8; nf++) {
                float p0 = __expf(sc[nf][2 * r] - mn);
                float p1 = __expf(sc[nf][2 * r + 1] - mn);
                sc[nf][2 * r] = p0;
                sc[nf][2 * r + 1] = p1;
                sum += p0 + p1;
            }
            sum += __shfl_xor_sync(0xffffffffu, sum, 1);
            sum += __shfl_xor_sync(0xffffffffu, sum, 2);
            l2s[r] = l2s[r] * alpha + sum;
            #pragma unroll
            for (int nf = 0; nf < 8; nf++) {
                o[nf][2 * r] *= alpha;
                o[nf][2 * r + 1] *= alpha;
            }
        }

        __syncthreads();    // all warps done reading Ks before P overwrite

        // Store P (tf32-rounded) into Ps (= Ks region), own rows only
        #pragma unroll
        for (int nf = 0; nf < 8; nf++) {
            int r0 = 16 * w + g;
            Ps[r0 * ST + nf * 8 + 2 * t]       = __uint_as_float(f2tf(sc[nf][0]));
            Ps[r0 * ST + nf * 8 + 2 * t + 1]   = __uint_as_float(f2tf(sc[nf][1]));
            Ps[(r0 + 8) * ST + nf * 8 + 2 * t]     = __uint_as_float(f2tf(sc[nf][2]));
            Ps[(r0 + 8) * ST + nf * 8 + 2 * t + 1] = __uint_as_float(f2tf(sc[nf][3]));
        }
        __syncwarp();       // cross-lane P visibility within warp

        // O += P @ V
        #pragma unroll
        for (int ks = 0; ks < 8; ks++) {
            int r0 = 16 * w + g;
            unsigned a0 = __float_as_uint(Ps[r0 * ST + ks * 8 + t]);
            unsigned a1 = __float_as_uint(Ps[(r0 + 8) * ST + ks * 8 + t]);
            unsigned a2 = __float_as_uint(Ps[r0 * ST + ks * 8 + t + 4]);
            unsigned a3 = __float_as_uint(Ps[(r0 + 8) * ST + ks * 8 + t + 4]);
            #pragma unroll
            for (int nf = 0; nf < 8; nf++) {
                unsigned b0 = __float_as_uint(Vs[(ks * 8 + t) * ST + nf * 8 + g]);
                unsigned b1 = __float_as_uint(Vs[(ks * 8 + t + 4) * ST + nf * 8 + g]);
                mma8(o[nf], a0, a1, a2, a3, b0, b1);
            }
        }
    }

    // Normalize + write out[b, t, h*64 + d]
    #pragma unroll
    for (int r = 0; r < 2; r++) {
        float inv = 1.f / l2s[r];
        int row = t0 + 16 * w + g + 8 * r;
        #pragma unroll
        for (int nf = 0; nf < 8; nf++) {
            int col = h * HDD + nf * 8 + 2 * t;
            float2 v = make_float2(o[nf][2 * r] * inv, o[nf][2 * r + 1] * inv);
            *reinterpret_cast<float2*>(
                &out[(size_t)(b * TT + row) * DD + col]) = v;
        }
    }
}

// ---------------------------------------------------------------------------
extern "C" void kernel_launch(void* const* d_in, const int* in_sizes, int n_in,
                              void* d_out, int out_size)
{
    const float* x     = (const float*)d_in[0];
    const float* w_qkv = (const float*)d_in[1];
    const float* b_qkv = (const float*)d_in[2];
    const float* w_out = (const float*)d_in[3];
    const float* b_out = (const float*)d_in[4];
    float* out = (float*)d_out;

    float* qkv;  cudaGetSymbolAddress((void**)&qkv,  g_qkv);
    float* attn; cudaGetSymbolAddress((void**)&attn, g_attn);

    const int ATTN_SMEM = 3 * 64 * 72 * (int)sizeof(float);  // 55296 B
    cudaFuncSetAttribute(attn_tc_kernel,
                         cudaFuncAttributeMaxDynamicSharedMemorySize, ATTN_SMEM);

    // 1) QKV projection: [16384,1024] @ [1024,3072] + b
    dim3 g1(3 * DD / 128, BB * TT / 128);
    gemm_tc_kernel<<<g1, 256>>>(x, w_qkv, b_qkv, qkv, BB * TT, 3 * DD, DD);

    // 2) Attention
    dim3 ga(TT / 64, HH, BB);
    attn_tc_kernel<<<ga, 128, ATTN_SMEM>>>(qkv, attn);

    // 3) Output projection: [16384,1024] @ [1024,1024] + b
    dim3 g3(DD / 128, BB * TT / 128);
    gemm_tc_kernel<<<g3, 256>>>(attn, w_out, b_out, out, BB * TT, DD, DD);
}

// round 4
// speedup vs baseline: 1.4036x; 1.2663x over previous
#include <cuda_runtime.h>
#include <cuda_bf16.h>
#include <math.h>

#define BB 16
#define TT 1024
#define DD 1024
#define HH 16
#define HDD 64

// Scratch (allocation-free rule: __device__ globals)
__device__ float g_qkv[BB * TT * 3 * DD];   // [B, T, 3D]
__device__ float g_attn[BB * TT * DD];      // [B, T, D]

// ---------------------------------------------------------------------------
// helpers
// ---------------------------------------------------------------------------
__device__ __forceinline__ unsigned f2tf(float x) {
    unsigned r;
    asm("cvt.rna.tf32.f32 %0, %1;" : "=r"(r) : "f"(x));
    return r;
}

// m16n8k8 tf32 MMA, fp32 accumulate (attention)
__device__ __forceinline__ void mma8(float* c,
                                     unsigned a0, unsigned a1, unsigned a2, unsigned a3,
                                     unsigned b0, unsigned b1) {
    asm volatile(
        "mma.sync.aligned.m16n8k8.row.col.f32.tf32.tf32.f32 "
        "{%0,%1,%2,%3}, {%4,%5,%6,%7}, {%8,%9}, {%0,%1,%2,%3};"
        : "+f"(c[0]), "+f"(c[1]), "+f"(c[2]), "+f"(c[3])
        : "r"(a0), "r"(a1), "r"(a2), "r"(a3), "r"(b0), "r"(b1));
}

// m16n8k16 bf16 MMA, fp32 accumulate (projections)
__device__ __forceinline__ void mma16(float* c,
                                      unsigned a0, unsigned a1, unsigned a2, unsigned a3,
                                      unsigned b0, unsigned b1) {
    asm volatile(
        "mma.sync.aligned.m16n8k16.row.col.f32.bf16.bf16.f32 "
        "{%0,%1,%2,%3}, {%4,%5,%6,%7}, {%8,%9}, {%0,%1,%2,%3};"
        : "+f"(c[0]), "+f"(c[1]), "+f"(c[2]), "+f"(c[3])
        : "r"(a0), "r"(a1), "r"(a2), "r"(a3), "r"(b0), "r"(b1));
}

__device__ __forceinline__ void bf16split(float x, __nv_bfloat16& hi, __nv_bfloat16& lo) {
    hi = __float2bfloat16(x);
    lo = __float2bfloat16(x - __bfloat162float(hi));
}

__device__ __forceinline__ unsigned pack2(__nv_bfloat16 a, __nv_bfloat16 b) {
    __nv_bfloat162 v(a, b);
    return *reinterpret_cast<unsigned*>(&v);
}

// ---------------------------------------------------------------------------
// bf16x2-split tensor-core GEMM with bias: C[M,N] = A[M,K] @ W[K,N] + bias[N]
// BM=BN=128, BK=32, 256 threads = 8 warps (4 row x 2 col), warp tile 32x64.
// fp32 -> (hi,lo) bf16 split done ONCE at smem-store time.
// Smem: AsH/AsL [row 128][k 32] stride 40 bf16; BsH/BsL [n 128][k 32] stride 40.
// Fragment loads are conflict-free: bank = (row*20 + t) mod 32 distinct per lane.
// ---------------------------------------------------------------------------
__global__ void __launch_bounds__(256, 2)
gemm_tc_kernel(const float* __restrict__ A,
               const float* __restrict__ W,
               const float* __restrict__ bias,
               float* __restrict__ C,
               int M, int N, int K)
{
    constexpr int BK = 32;
    constexpr int SST = 40;      // bf16 element stride
    __shared__ __nv_bfloat16 AsH[128 * SST];
    __shared__ __nv_bfloat16 AsL[128 * SST];
    __shared__ __nv_bfloat16 BsH[128 * SST];
    __shared__ __nv_bfloat16 BsL[128 * SST];

    const int tid = threadIdx.x;
    const int wid = tid >> 5;
    const int wr = wid & 3;          // warp row (4)
    const int wc = wid >> 2;         // warp col (2)
    const int lane = tid & 31;
    const int g = lane >> 2;         // quad id
    const int t = lane & 3;          // thread-in-quad
    const int blockRow = blockIdx.y * 128;
    const int blockCol = blockIdx.x * 128;

    float c[2][8][4];
    #pragma unroll
    for (int mf = 0; mf < 2; mf++)
        #pragma unroll
        for (int nf = 0; nf < 8; nf++)
            #pragma unroll
            for (int i = 0; i < 4; i++) c[mf][nf][i] = 0.f;

    float4 pa[4], pb[4];

    auto prefetch = [&](int kt) {
        #pragma unroll
        for (int l = 0; l < 4; l++) {
            int s = tid + l * 256;              // 1024 float4 slots
            int r = s >> 3, c4 = (s & 7) * 4;
            pa[l] = *reinterpret_cast<const float4*>(
                &A[(size_t)(blockRow + r) * K + kt + c4]);
        }
        #pragma unroll
        for (int l = 0; l < 4; l++) {
            int s = tid + l * 256;
            int r = s >> 5, c4 = (s & 31) * 4;
            pb[l] = *reinterpret_cast<const float4*>(
                &W[(size_t)(kt + r) * N + blockCol + c4]);
        }
    };

    prefetch(0);

    for (int kt = 0; kt < K; kt += BK) {
        __syncthreads();
        // A tile: [row][k], hi/lo split, vectorized 4-bf16 stores
        #pragma unroll
        for (int l = 0; l < 4; l++) {
            int s = tid + l * 256;
            int r = s >> 3, c4 = (s & 7) * 4;
            float f[4] = {pa[l].x, pa[l].y, pa[l].z, pa[l].w};
            __nv_bfloat16 h[4], lo[4];
            #pragma unroll
            for (int j = 0; j < 4; j++) bf16split(f[j], h[j], lo[j]);
            uint2 vh = make_uint2(pack2(h[0], h[1]), pack2(h[2], h[3]));
            uint2 vl = make_uint2(pack2(lo[0], lo[1]), pack2(lo[2], lo[3]));
            *reinterpret_cast<uint2*>(&AsH[r * SST + c4]) = vh;
            *reinterpret_cast<uint2*>(&AsL[r * SST + c4]) = vl;
        }
        // B tile: global [k][n] -> smem [n][k] transposed, hi/lo split
        #pragma unroll
        for (int l = 0; l < 4; l++) {
            int s = tid + l * 256;
            int r = s >> 5, c4 = (s & 31) * 4;     // r = k row, c4 = n base
            float f[4] = {pb[l].x, pb[l].y, pb[l].z, pb[l].w};
            #pragma unroll
            for (int j = 0; j < 4; j++) {
                __nv_bfloat16 h, lo;
                bf16split(f[j], h, lo);
                BsH[(c4 + j) * SST + r] = h;
                BsL[(c4 + j) * SST + r] = lo;
            }
        }
        __syncthreads();

        if (kt + BK < K) prefetch(kt + BK);

        #pragma unroll
        for (int ks = 0; ks < 2; ks++) {
            const int kb = ks * 16;
            unsigned ah[2][4], al_[2][4];
            #pragma unroll
            for (int mf = 0; mf < 2; mf++) {
                int r0 = wr * 32 + mf * 16 + g;
                ah[mf][0] = *reinterpret_cast<const unsigned*>(&AsH[r0 * SST + kb + 2 * t]);
                ah[mf][1] = *reinterpret_cast<const unsigned*>(&AsH[(r0 + 8) * SST + kb + 2 * t]);
                ah[mf][2] = *reinterpret_cast<const unsigned*>(&AsH[r0 * SST + kb + 2 * t + 8]);
                ah[mf][3] = *reinterpret_cast<const unsigned*>(&AsH[(r0 + 8) * SST + kb + 2 * t + 8]);
                al_[mf][0] = *reinterpret_cast<const unsigned*>(&AsL[r0 * SST + kb + 2 * t]);
                al_[mf][1] = *reinterpret_cast<const unsigned*>(&AsL[(r0 + 8) * SST + kb + 2 * t]);
                al_[mf][2] = *reinterpret_cast<const unsigned*>(&AsL[r0 * SST + kb + 2 * t + 8]);
                al_[mf][3] = *reinterpret_cast<const unsigned*>(&AsL[(r0 + 8) * SST + kb + 2 * t + 8]);
            }
            #pragma unroll
            for (int nf = 0; nf < 8; nf++) {
                int n = wc * 64 + nf * 8 + g;
                unsigned bh0 = *reinterpret_cast<const unsigned*>(&BsH[n * SST + kb + 2 * t]);
                unsigned bh1 = *reinterpret_cast<const unsigned*>(&BsH[n * SST + kb + 2 * t + 8]);
                unsigned bl0 = *reinterpret_cast<const unsigned*>(&BsL[n * SST + kb + 2 * t]);
                unsigned bl1 = *reinterpret_cast<const unsigned*>(&BsL[n * SST + kb + 2 * t + 8]);
                #pragma unroll
                for (int mf = 0; mf < 2; mf++) {
                    mma16(c[mf][nf], ah[mf][0], ah[mf][1], ah[mf][2], ah[mf][3], bh0, bh1);
                    mma16(c[mf][nf], ah[mf][0], ah[mf][1], ah[mf][2], ah[mf][3], bl0, bl1);
                    mma16(c[mf][nf], al_[mf][0], al_[mf][1], al_[mf][2], al_[mf][3], bh0, bh1);
                }
            }
        }
    }

    // Writeback with bias (c layout identical to k8 variant)
    #pragma unroll
    for (int mf = 0; mf < 2; mf++) {
        int row = blockRow + wr * 32 + mf * 16 + g;
        #pragma unroll
        for (int nf = 0; nf < 8; nf++) {
            int col = blockCol + wc * 64 + nf * 8 + 2 * t;
            float bx = bias[col], by = bias[col + 1];
            float2 v0 = make_float2(c[mf][nf][0] + bx, c[mf][nf][1] + by);
            float2 v1 = make_float2(c[mf][nf][2] + bx, c[mf][nf][3] + by);
            *reinterpret_cast<float2*>(&C[(size_t)row * N + col]) = v0;
            *reinterpret_cast<float2*>(&C[(size_t)(row + 8) * N + col]) = v1;
        }
    }
}

// ---------------------------------------------------------------------------
// Flash attention, tf32 tensor cores (unchanged from passing round-2 version).
// ---------------------------------------------------------------------------
__global__ void __launch_bounds__(128, 4)
attn_tc_kernel(const float* __restrict__ qkv, float* __restrict__ out)
{
    constexpr int ST = 72;
    extern __shared__ float sm[];
    float* Qs = sm;                  // [64][72]
    float* Ks = sm + 64 * ST;        // [64][72]; reused as Ps
    float* Vs = sm + 2 * 64 * ST;    // [64][72]
    float* Ps = Ks;

    const int b = blockIdx.z;
    const int h = blockIdx.y;
    const int qt = blockIdx.x;
    const int tid = threadIdx.x;
    const int w = tid >> 5;
    const int lane = tid & 31;
    const int g = lane >> 2;
    const int t = lane & 3;
    const int t0 = qt * 64;
    const float scale = 0.125f;

    const float* qbase = qkv + (size_t)b * TT * 3 * DD + h * HDD;

    #pragma unroll
    for (int l = 0; l < 8; l++) {
        int s = tid + l * 128;
        int r = s >> 4, c4 = (s & 15) * 4;
        float4 v = *reinterpret_cast<const float4*>(
            qbase + (size_t)(t0 + r) * 3 * DD + c4);
        Qs[r * ST + c4 + 0] = __uint_as_float(f2tf(v.x * scale));
        Qs[r * ST + c4 + 1] = __uint_as_float(f2tf(v.y * scale));
        Qs[r * ST + c4 + 2] = __uint_as_float(f2tf(v.z * scale));
        Qs[r * ST + c4 + 3] = __uint_as_float(f2tf(v.w * scale));
    }

    float o[8][4];
    #pragma unroll
    for (int nf = 0; nf < 8; nf++)
        #pragma unroll
        for (int i = 0; i < 4; i++) o[nf][i] = 0.f;
    float m[2] = {-1e30f, -1e30f};
    float l2s[2] = {0.f, 0.f};

    for (int kt = 0; kt < TT / 64; kt++) {
        __syncthreads();
        #pragma unroll
        for (int ls = 0; ls < 8; ls++) {
            int s = tid + ls * 128;
            int r = s >> 4, c4 = (s & 15) * 4;
            const float* krow = qbase + DD + (size_t)(kt * 64 + r) * 3 * DD;
            const float* vrow = qbase + 2 * DD + (size_t)(kt * 64 + r) * 3 * DD;
            float4 kv = *reinterpret_cast<const float4*>(krow + c4);
            Ks[r * ST + c4 + 0] = __uint_as_float(f2tf(kv.x));
            Ks[r * ST + c4 + 1] = __uint_as_float(f2tf(kv.y));
            Ks[r * ST + c4 + 2] = __uint_as_float(f2tf(kv.z));
            Ks[r * ST + c4 + 3] = __uint_as_float(f2tf(kv.w));
            float4 vv = *reinterpret_cast<const float4*>(vrow + c4);
            Vs[r * ST + c4 + 0] = __uint_as_float(f2tf(vv.x));
            Vs[r * ST + c4 + 1] = __uint_as_float(f2tf(vv.y));
            Vs[r * ST + c4 + 2] = __uint_as_float(f2tf(vv.z));
            Vs[r * ST + c4 + 3] = __uint_as_float(f2tf(vv.w));
        }
        __syncthreads();

        float sc[8][4];
        #pragma unroll
        for (int nf = 0; nf < 8; nf++)
            #pragma unroll
            for (int i = 0; i < 4; i++) sc[nf][i] = 0.f;

        #pragma unroll
        for (int ks = 0; ks < 8; ks++) {
            int r0 = 16 * w + g;
            unsigned a0 = __float_as_uint(Qs[r0 * ST + ks * 8 + t]);
            unsigned a1 = __float_as_uint(Qs[(r0 + 8) * ST + ks * 8 + t]);
            unsigned a2 = __float_as_uint(Qs[r0 * ST + ks * 8 + t + 4]);
            unsigned a3 = __float_as_uint(Qs[(r0 + 8) * ST + ks * 8 + t + 4]);
            #pragma unroll
            for (int nf = 0; nf < 8; nf++) {
                unsigned b0 = __float_as_uint(Ks[(nf * 8 + g) * ST + ks * 8 + t]);
                unsigned b1 = __float_as_uint(Ks[(nf * 8 + g) * ST + ks * 8 + t + 4]);
                mma8(sc[nf], a0, a1, a2, a3, b0, b1);
            }
        }

        #pragma unroll
        for (int r = 0; r < 2; r++) {
            float mx = -1e30f;
            #pragma unroll
            for (int nf = 0; nf < 8; nf++)
                mx = fmaxf(mx, fmaxf(sc[nf][2 * r], sc[nf][2 * r + 1]));
            mx = fmaxf(mx, __shfl_xor_sync(0xffffffffu, mx, 1));
            mx = fmaxf(mx, __shfl_xor_sync(0xffffffffu, mx, 2));
            float mn = fmaxf(m[r], mx);
            float alpha = __expf(m[r] - mn);
            m[r] = mn;
            float sum = 0.f;
            #pragma unroll
            for (int nf = 0; nf < 8; nf++) {
                float p0 = __expf(sc[nf][2 * r] - mn);
                float p1 = __expf(sc[nf][2 * r + 1] - mn);
                sc[nf][2 * r] = p0;
                sc[nf][2 * r + 1] = p1;
                sum += p0 + p1;
            }
            sum += __shfl_xor_sync(0xffffffffu, sum, 1);
            sum += __shfl_xor_sync(0xffffffffu, sum, 2);
            l2s[r] = l2s[r] * alpha + sum;
            #pragma unroll
            for (int nf = 0; nf < 8; nf++) {
                o[nf][2 * r] *= alpha;
                o[nf][2 * r + 1] *= alpha;
            }
        }

        __syncthreads();

        #pragma unroll
        for (int nf = 0; nf < 8; nf++) {
            int r0 = 16 * w + g;
            Ps[r0 * ST + nf * 8 + 2 * t]       = __uint_as_float(f2tf(sc[nf][0]));
            Ps[r0 * ST + nf * 8 + 2 * t + 1]   = __uint_as_float(f2tf(sc[nf][1]));
            Ps[(r0 + 8) * ST + nf * 8 + 2 * t]     = __uint_as_float(f2tf(sc[nf][2]));
            Ps[(r0 + 8) * ST + nf * 8 + 2 * t + 1] = __uint_as_float(f2tf(sc[nf][3]));
        }
        __syncwarp();

        #pragma unroll
        for (int ks = 0; ks < 8; ks++) {
            int r0 = 16 * w + g;
            unsigned a0 = __float_as_uint(Ps[r0 * ST + ks * 8 + t]);
            unsigned a1 = __float_as_uint(Ps[(r0 + 8) * ST + ks * 8 + t]);
            unsigned a2 = __float_as_uint(Ps[r0 * ST + ks * 8 + t + 4]);
            unsigned a3 = __float_as_uint(Ps[(r0 + 8) * ST + ks * 8 + t + 4]);
            #pragma unroll
            for (int nf = 0; nf < 8; nf++) {
                unsigned b0 = __float_as_uint(Vs[(ks * 8 + t) * ST + nf * 8 + g]);
                unsigned b1 = __float_as_uint(Vs[(ks * 8 + t + 4) * ST + nf * 8 + g]);
                mma8(o[nf], a0, a1, a2, a3, b0, b1);
            }
        }
    }

    #pragma unroll
    for (int r = 0; r < 2; r++) {
        float inv = 1.f / l2s[r];
        int row = t0 + 16 * w + g + 8 * r;
        #pragma unroll
        for (int nf = 0; nf < 8; nf++) {
            int col = h * HDD + nf * 8 + 2 * t;
            float2 v = make_float2(o[nf][2 * r] * inv, o[nf][2 * r + 1] * inv);
            *reinterpret_cast<float2*>(
                &out[(size_t)(b * TT + row) * DD + col]) = v;
        }
    }
}

// ---------------------------------------------------------------------------
extern "C" void kernel_launch(void* const* d_in, const int* in_sizes, int n_in,
                              void* d_out, int out_size)
{
    const float* x     = (const float*)d_in[0];
    const float* w_qkv = (const float*)d_in[1];
    const float* b_qkv = (const float*)d_in[2];
    const float* w_out = (const float*)d_in[3];
    const float* b_out = (const float*)d_in[4];
    float* out = (float*)d_out;

    float* qkv;  cudaGetSymbolAddress((void**)&qkv,  g_qkv);
    float* attn; cudaGetSymbolAddress((void**)&attn, g_attn);

    const int ATTN_SMEM = 3 * 64 * 72 * (int)sizeof(float);  // 55296 B
    cudaFuncSetAttribute(attn_tc_kernel,
                         cudaFuncAttributeMaxDynamicSharedMemorySize, ATTN_SMEM);

    // 1) QKV projection: [16384,1024] @ [1024,3072] + b
    dim3 g1(3 * DD / 128, BB * TT / 128);
    gemm_tc_kernel<<<g1, 256>>>(x, w_qkv, b_qkv, qkv, BB * TT, 3 * DD, DD);

    // 2) Attention
    dim3 ga(TT / 64, HH, BB);
    attn_tc_kernel<<<ga, 128, ATTN_SMEM>>>(qkv, attn);

    // 3) Output projection: [16384,1024] @ [1024,1024] + b
    dim3 g3(DD / 128, BB * TT / 128);
    gemm_tc_kernel<<<g3, 256>>>(attn, w_out, b_out, out, BB * TT, DD, DD);
}

// round 5
// speedup vs baseline: 2.7357x; 1.9491x over previous
#include <cuda_runtime.h>
#include <cuda_bf16.h>
#include <math.h>

#define BB 16
#define TT 1024
#define DD 1024
#define HH 16
#define HDD 64

// Scratch (allocation-free rule: __device__ globals)
__device__ float g_qkv[BB * TT * 3 * DD];   // [B, T, 3D]
__device__ float g_attn[BB * TT * DD];      // [B, T, D]

// ---------------------------------------------------------------------------
// helpers
// ---------------------------------------------------------------------------
__device__ __forceinline__ unsigned ssa(const void* p) {
    return (unsigned)__cvta_generic_to_shared(p);
}

__device__ __forceinline__ void ldsm4(unsigned& r0, unsigned& r1,
                                      unsigned& r2, unsigned& r3, unsigned a) {
    asm volatile("ldmatrix.sync.aligned.m8n8.x4.shared.b16 {%0,%1,%2,%3}, [%4];"
                 : "=r"(r0), "=r"(r1), "=r"(r2), "=r"(r3) : "r"(a));
}

__device__ __forceinline__ void ldsm4t(unsigned& r0, unsigned& r1,
                                       unsigned& r2, unsigned& r3, unsigned a) {
    asm volatile("ldmatrix.sync.aligned.m8n8.x4.trans.shared.b16 {%0,%1,%2,%3}, [%4];"
                 : "=r"(r0), "=r"(r1), "=r"(r2), "=r"(r3) : "r"(a));
}

// m16n8k16 bf16 MMA, fp32 accumulate
__device__ __forceinline__ void mma16(float* c,
                                      unsigned a0, unsigned a1, unsigned a2, unsigned a3,
                                      unsigned b0, unsigned b1) {
    asm volatile(
        "mma.sync.aligned.m16n8k16.row.col.f32.bf16.bf16.f32 "
        "{%0,%1,%2,%3}, {%4,%5,%6,%7}, {%8,%9}, {%0,%1,%2,%3};"
        : "+f"(c[0]), "+f"(c[1]), "+f"(c[2]), "+f"(c[3])
        : "r"(a0), "r"(a1), "r"(a2), "r"(a3), "r"(b0), "r"(b1));
}

__device__ __forceinline__ void bf16split(float x, __nv_bfloat16& hi, __nv_bfloat16& lo) {
    hi = __float2bfloat16(x);
    lo = __float2bfloat16(x - __bfloat162float(hi));
}

__device__ __forceinline__ unsigned pack2(__nv_bfloat16 a, __nv_bfloat16 b) {
    __nv_bfloat162 v(a, b);
    return *reinterpret_cast<unsigned*>(&v);
}

// ---------------------------------------------------------------------------
// bf16x2-split tensor-core GEMM with bias, ldmatrix fragment loads.
// BM=BN=128, BK=32, 256 threads = 8 warps (4 row x 2 col), warp tile 32x64.
// A smem: [row 128][k 32] stride 40 bf16 (hi/lo).  ldmatrix.x4 (row 80B ≡ 20w)
// B smem: [k 32][n 128] stride 136 bf16 (hi/lo).   ldmatrix.x4.trans (272B ≡ 4w)
// Both conflict-free.
// ---------------------------------------------------------------------------
__global__ void __launch_bounds__(256, 2)
gemm_tc_kernel(const float* __restrict__ A,
               const float* __restrict__ W,
               const float* __restrict__ bias,
               float* __restrict__ C,
               int M, int N, int K)
{
    constexpr int BK = 32;
    constexpr int AST = 40;
    constexpr int BST = 136;
    __shared__ __align__(16) __nv_bfloat16 AsH[128 * AST];
    __shared__ __align__(16) __nv_bfloat16 AsL[128 * AST];
    __shared__ __align__(16) __nv_bfloat16 BsH[BK * BST];
    __shared__ __align__(16) __nv_bfloat16 BsL[BK * BST];

    const int tid = threadIdx.x;
    const int wid = tid >> 5;
    const int wr = wid & 3;
    const int wc = wid >> 2;
    const int lane = tid & 31;
    const int g = lane >> 2;
    const int t = lane & 3;
    const int blockRow = blockIdx.y * 128;
    const int blockCol = blockIdx.x * 128;

    // ldmatrix lane -> tile decomposition (shared by all fragment loads)
    const int lr   = lane & 7;            // row within 8-row tile
    const int tlo  = (lane >> 3) & 1;     // tile bit 0
    const int thi  = lane >> 4;           // tile bit 1

    float c[2][8][4];
    #pragma unroll
    for (int mf = 0; mf < 2; mf++)
        #pragma unroll
        for (int nf = 0; nf < 8; nf++)
            #pragma unroll
            for (int i = 0; i < 4; i++) c[mf][nf][i] = 0.f;

    float4 pa[4], pb[4];
    auto prefetch = [&](int kt) {
        #pragma unroll
        for (int l = 0; l < 4; l++) {
            int s = tid + l * 256;
            int r = s >> 3, c4 = (s & 7) * 4;
            pa[l] = *reinterpret_cast<const float4*>(
                &A[(size_t)(blockRow + r) * K + kt + c4]);
        }
        #pragma unroll
        for (int l = 0; l < 4; l++) {
            int s = tid + l * 256;
            int r = s >> 5, c4 = (s & 31) * 4;
            pb[l] = *reinterpret_cast<const float4*>(
                &W[(size_t)(kt + r) * N + blockCol + c4]);
        }
    };

    prefetch(0);

    for (int kt = 0; kt < K; kt += BK) {
        __syncthreads();
        // A tile store: [row][k], hi/lo split, uint2 (4 bf16) stores
        #pragma unroll
        for (int l = 0; l < 4; l++) {
            int s = tid + l * 256;
            int r = s >> 3, c4 = (s & 7) * 4;
            float f[4] = {pa[l].x, pa[l].y, pa[l].z, pa[l].w};
            __nv_bfloat16 h[4], lo[4];
            #pragma unroll
            for (int j = 0; j < 4; j++) bf16split(f[j], h[j], lo[j]);
            *reinterpret_cast<uint2*>(&AsH[r * AST + c4]) =
                make_uint2(pack2(h[0], h[1]), pack2(h[2], h[3]));
            *reinterpret_cast<uint2*>(&AsL[r * AST + c4]) =
                make_uint2(pack2(lo[0], lo[1]), pack2(lo[2], lo[3]));
        }
        // B tile store: [k][n] (no transpose), uint2 stores
        #pragma unroll
        for (int l = 0; l < 4; l++) {
            int s = tid + l * 256;
            int r = s >> 5, c4 = (s & 31) * 4;
            float f[4] = {pb[l].x, pb[l].y, pb[l].z, pb[l].w};
            __nv_bfloat16 h[4], lo[4];
            #pragma unroll
            for (int j = 0; j < 4; j++) bf16split(f[j], h[j], lo[j]);
            *reinterpret_cast<uint2*>(&BsH[r * BST + c4]) =
                make_uint2(pack2(h[0], h[1]), pack2(h[2], h[3]));
            *reinterpret_cast<uint2*>(&BsL[r * BST + c4]) =
                make_uint2(pack2(lo[0], lo[1]), pack2(lo[2], lo[3]));
        }
        __syncthreads();

        if (kt + BK < K) prefetch(kt + BK);

        #pragma unroll
        for (int ks = 0; ks < 2; ks++) {
            const int kb = ks * 16;
            unsigned ah[2][4], al_[2][4];
            #pragma unroll
            for (int mf = 0; mf < 2; mf++) {
                int row = wr * 32 + mf * 16 + tlo * 8 + lr;
                int col = kb + thi * 8;
                ldsm4(ah[mf][0], ah[mf][1], ah[mf][2], ah[mf][3],
                      ssa(&AsH[row * AST + col]));
                ldsm4(al_[mf][0], al_[mf][1], al_[mf][2], al_[mf][3],
                      ssa(&AsL[row * AST + col]));
            }
            #pragma unroll
            for (int np = 0; np < 4; np++) {
                int n0 = wc * 64 + np * 16;
                int krow = kb + tlo * 8 + lr;
                int ncol = n0 + thi * 8;
                unsigned bh[4], bl[4];
                ldsm4t(bh[0], bh[1], bh[2], bh[3], ssa(&BsH[krow * BST + ncol]));
                ldsm4t(bl[0], bl[1], bl[2], bl[3], ssa(&BsL[krow * BST + ncol]));
                #pragma unroll
                for (int half = 0; half < 2; half++) {
                    int nf = np * 2 + half;
                    unsigned b0h = bh[2 * half], b1h = bh[2 * half + 1];
                    unsigned b0l = bl[2 * half], b1l = bl[2 * half + 1];
                    #pragma unroll
                    for (int mf = 0; mf < 2; mf++) {
                        mma16(c[mf][nf], ah[mf][0], ah[mf][1], ah[mf][2], ah[mf][3], b0h, b1h);
                        mma16(c[mf][nf], ah[mf][0], ah[mf][1], ah[mf][2], ah[mf][3], b0l, b1l);
                        mma16(c[mf][nf], al_[mf][0], al_[mf][1], al_[mf][2], al_[mf][3], b0h, b1h);
                    }
                }
            }
        }
    }

    #pragma unroll
    for (int mf = 0; mf < 2; mf++) {
        int row = blockRow + wr * 32 + mf * 16 + g;
        #pragma unroll
        for (int nf = 0; nf < 8; nf++) {
            int col = blockCol + wc * 64 + nf * 8 + 2 * t;
            float bx = bias[col], by = bias[col + 1];
            float2 v0 = make_float2(c[mf][nf][0] + bx, c[mf][nf][1] + by);
            float2 v1 = make_float2(c[mf][nf][2] + bx, c[mf][nf][3] + by);
            *reinterpret_cast<float2*>(&C[(size_t)row * N + col]) = v0;
            *reinterpret_cast<float2*>(&C[(size_t)(row + 8) * N + col]) = v1;
        }
    }
}

// ---------------------------------------------------------------------------
// Flash attention, bf16 3-term split (~17-bit effective), ldmatrix loads,
// P kept in registers (S C-fragment layout == PV A-fragment layout).
// Block = 64 q rows of one (b,h); 128 threads = 4 warps; warp w owns rows 16w..
// Smem (bf16, stride 72): QH/QL, KH/KL, VH/VL  [64][72] each = 55296 B total.
// ---------------------------------------------------------------------------
__global__ void __launch_bounds__(128, 4)
attn_tc_kernel(const float* __restrict__ qkv, float* __restrict__ out)
{
    constexpr int AT = 72;
    extern __shared__ __nv_bfloat16 smb[];
    __nv_bfloat16* QH = smb;
    __nv_bfloat16* QL = smb + 64 * AT;
    __nv_bfloat16* KH = smb + 2 * 64 * AT;
    __nv_bfloat16* KL = smb + 3 * 64 * AT;
    __nv_bfloat16* VH = smb + 4 * 64 * AT;
    __nv_bfloat16* VL = smb + 5 * 64 * AT;

    const int b = blockIdx.z;
    const int h = blockIdx.y;
    const int qt = blockIdx.x;
    const int tid = threadIdx.x;
    const int w = tid >> 5;
    const int lane = tid & 31;
    const int g = lane >> 2;
    const int t = lane & 3;
    const int lr  = lane & 7;
    const int tlo = (lane >> 3) & 1;
    const int thi = lane >> 4;
    const int t0 = qt * 64;
    const float scale = 0.125f;

    const float* qbase = qkv + (size_t)b * TT * 3 * DD + h * HDD;

    // Load Q (scaled, hi/lo split)
    #pragma unroll
    for (int l = 0; l < 8; l++) {
        int s = tid + l * 128;
        int r = s >> 4, c4 = (s & 15) * 4;
        float4 v = *reinterpret_cast<const float4*>(
            qbase + (size_t)(t0 + r) * 3 * DD + c4);
        float f[4] = {v.x * scale, v.y * scale, v.z * scale, v.w * scale};
        __nv_bfloat16 hh[4], ll[4];
        #pragma unroll
        for (int j = 0; j < 4; j++) bf16split(f[j], hh[j], ll[j]);
        *reinterpret_cast<uint2*>(&QH[r * AT + c4]) =
            make_uint2(pack2(hh[0], hh[1]), pack2(hh[2], hh[3]));
        *reinterpret_cast<uint2*>(&QL[r * AT + c4]) =
            make_uint2(pack2(ll[0], ll[1]), pack2(ll[2], ll[3]));
    }

    float o[8][4];
    #pragma unroll
    for (int nf = 0; nf < 8; nf++)
        #pragma unroll
        for (int i = 0; i < 4; i++) o[nf][i] = 0.f;
    float m[2] = {-1e30f, -1e30f};
    float l2s[2] = {0.f, 0.f};

    for (int kt = 0; kt < TT / 64; kt++) {
        __syncthreads();    // prev tile consumed (also orders Q on iter 0)
        // Load K, V tiles (hi/lo split)
        #pragma unroll
        for (int ls = 0; ls < 8; ls++) {
            int s = tid + ls * 128;
            int r = s >> 4, c4 = (s & 15) * 4;
            const float* krow = qbase + DD + (size_t)(kt * 64 + r) * 3 * DD;
            const float* vrow = qbase + 2 * DD + (size_t)(kt * 64 + r) * 3 * DD;
            float4 kv = *reinterpret_cast<const float4*>(krow + c4);
            float kf[4] = {kv.x, kv.y, kv.z, kv.w};
            __nv_bfloat16 hh[4], ll[4];
            #pragma unroll
            for (int j = 0; j < 4; j++) bf16split(kf[j], hh[j], ll[j]);
            *reinterpret_cast<uint2*>(&KH[r * AT + c4]) =
                make_uint2(pack2(hh[0], hh[1]), pack2(hh[2], hh[3]));
            *reinterpret_cast<uint2*>(&KL[r * AT + c4]) =
                make_uint2(pack2(ll[0], ll[1]), pack2(ll[2], ll[3]));
            float4 vv = *reinterpret_cast<const float4*>(vrow + c4);
            float vf[4] = {vv.x, vv.y, vv.z, vv.w};
            #pragma unroll
            for (int j = 0; j < 4; j++) bf16split(vf[j], hh[j], ll[j]);
            *reinterpret_cast<uint2*>(&VH[r * AT + c4]) =
                make_uint2(pack2(hh[0], hh[1]), pack2(hh[2], hh[3]));
            *reinterpret_cast<uint2*>(&VL[r * AT + c4]) =
                make_uint2(pack2(ll[0], ll[1]), pack2(ll[2], ll[3]));
        }
        __syncthreads();

        // ---- S = Q @ K^T ----
        float sc[8][4];
        #pragma unroll
        for (int nf = 0; nf < 8; nf++)
            #pragma unroll
            for (int i = 0; i < 4; i++) sc[nf][i] = 0.f;

        #pragma unroll
        for (int ks = 0; ks < 4; ks++) {
            const int kb = ks * 16;
            unsigned qh[4], ql[4];
            {
                int row = 16 * w + tlo * 8 + lr;
                int col = kb + thi * 8;
                ldsm4(qh[0], qh[1], qh[2], qh[3], ssa(&QH[row * AT + col]));
                ldsm4(ql[0], ql[1], ql[2], ql[3], ssa(&QL[row * AT + col]));
            }
            #pragma unroll
            for (int np = 0; np < 4; np++) {
                int n0 = np * 16;
                // non-trans: tiles (n0-7,kb),(n0-7,kb+8),(n8-15,kb),(n8-15,kb+8)
                int row = n0 + thi * 8 + lr;
                int col = kb + tlo * 8;
                unsigned kh[4], kl[4];
                ldsm4(kh[0], kh[1], kh[2], kh[3], ssa(&KH[row * AT + col]));
                ldsm4(kl[0], kl[1], kl[2], kl[3], ssa(&KL[row * AT + col]));
                #pragma unroll
                for (int half = 0; half < 2; half++) {
                    int nf = np * 2 + half;
                    unsigned b0h = kh[2 * half], b1h = kh[2 * half + 1];
                    unsigned b0l = kl[2 * half], b1l = kl[2 * half + 1];
                    mma16(sc[nf], qh[0], qh[1], qh[2], qh[3], b0h, b1h);
                    mma16(sc[nf], qh[0], qh[1], qh[2], qh[3], b0l, b1l);
                    mma16(sc[nf], ql[0], ql[1], ql[2], ql[3], b0h, b1h);
                }
            }
        }

        // ---- online softmax ----
        #pragma unroll
        for (int r = 0; r < 2; r++) {
            float mx = -1e30f;
            #pragma unroll
            for (int nf = 0; nf < 8; nf++)
                mx = fmaxf(mx, fmaxf(sc[nf][2 * r], sc[nf][2 * r + 1]));
            mx = fmaxf(mx, __shfl_xor_sync(0xffffffffu, mx, 1));
            mx = fmaxf(mx, __shfl_xor_sync(0xffffffffu, mx, 2));
            float mn = fmaxf(m[r], mx);
            float alpha = __expf(m[r] - mn);
            m[r] = mn;
            float sum = 0.f;
            #pragma unroll
            for (int nf = 0; nf < 8; nf++) {
                float p0 = __expf(sc[nf][2 * r] - mn);
                float p1 = __expf(sc[nf][2 * r + 1] - mn);
                sc[nf][2 * r] = p0;
                sc[nf][2 * r + 1] = p1;
                sum += p0 + p1;
            }
            sum += __shfl_xor_sync(0xffffffffu, sum, 1);
            sum += __shfl_xor_sync(0xffffffffu, sum, 2);
            l2s[r] = l2s[r] * alpha + sum;
            #pragma unroll
            for (int nf = 0; nf < 8; nf++) {
                o[nf][2 * r] *= alpha;
                o[nf][2 * r + 1] *= alpha;
            }
        }

        // ---- O += P @ V  (P from registers: C-frag layout == A-frag layout) ----
        #pragma unroll
        for (int ks2 = 0; ks2 < 4; ks2++) {
            const int kb = ks2 * 16;
            unsigned pa_h[4], pa_l[4];
            #pragma unroll
            for (int half = 0; half < 2; half++) {
                const float* s4 = sc[2 * ks2 + half];
                __nv_bfloat16 h0, l0, h1, l1, h2, l2, h3, l3;
                bf16split(s4[0], h0, l0);
                bf16split(s4[1], h1, l1);
                bf16split(s4[2], h2, l2);
                bf16split(s4[3], h3, l3);
                pa_h[2 * half]     = pack2(h0, h1);
                pa_h[2 * half + 1] = pack2(h2, h3);
                pa_l[2 * half]     = pack2(l0, l1);
                pa_l[2 * half + 1] = pack2(l2, l3);
            }
            #pragma unroll
            for (int np = 0; np < 4; np++) {
                int n0 = np * 16;
                int vr = kb + tlo * 8 + lr;
                int vc = n0 + thi * 8;
                unsigned vh[4], vl[4];
                ldsm4t(vh[0], vh[1], vh[2], vh[3], ssa(&VH[vr * AT + vc]));
                ldsm4t(vl[0], vl[1], vl[2], vl[3], ssa(&VL[vr * AT + vc]));
                #pragma unroll
                for (int half = 0; half < 2; half++) {
                    int nfo = np * 2 + half;
                    unsigned b0h = vh[2 * half], b1h = vh[2 * half + 1];
                    unsigned b0l = vl[2 * half], b1l = vl[2 * half + 1];
                    mma16(o[nfo], pa_h[0], pa_h[1], pa_h[2], pa_h[3], b0h, b1h);
                    mma16(o[nfo], pa_h[0], pa_h[1], pa_h[2], pa_h[3], b0l, b1l);
                    mma16(o[nfo], pa_l[0], pa_l[1], pa_l[2], pa_l[3], b0h, b1h);
                }
            }
        }
    }

    // Normalize + write out[b, t, h*64 + d]
    #pragma unroll
    for (int r = 0; r < 2; r++) {
        float inv = 1.f / l2s[r];
        int row = t0 + 16 * w + g + 8 * r;
        #pragma unroll
        for (int nf = 0; nf < 8; nf++) {
            int col = h * HDD + nf * 8 + 2 * t;
            float2 v = make_float2(o[nf][2 * r] * inv, o[nf][2 * r + 1] * inv);
            *reinterpret_cast<float2*>(
                &out[(size_t)(b * TT + row) * DD + col]) = v;
        }
    }
}

// ---------------------------------------------------------------------------
extern "C" void kernel_launch(void* const* d_in, const int* in_sizes, int n_in,
                              void* d_out, int out_size)
{
    const float* x     = (const float*)d_in[0];
    const float* w_qkv = (const float*)d_in[1];
    const float* b_qkv = (const float*)d_in[2];
    const float* w_out = (const float*)d_in[3];
    const float* b_out = (const float*)d_in[4];
    float* out = (float*)d_out;

    float* qkv;  cudaGetSymbolAddress((void**)&qkv,  g_qkv);
    float* attn; cudaGetSymbolAddress((void**)&attn, g_attn);

    const int ATTN_SMEM = 6 * 64 * 72 * (int)sizeof(__nv_bfloat16);  // 55296 B
    cudaFuncSetAttribute(attn_tc_kernel,
                         cudaFuncAttributeMaxDynamicSharedMemorySize, ATTN_SMEM);

    // 1) QKV projection: [16384,1024] @ [1024,3072] + b
    dim3 g1(3 * DD / 128, BB * TT / 128);
    gemm_tc_kernel<<<g1, 256>>>(x, w_qkv, b_qkv, qkv, BB * TT, 3 * DD, DD);

    // 2) Attention
    dim3 ga(TT / 64, HH, BB);
    attn_tc_kernel<<<ga, 128, ATTN_SMEM>>>(qkv, attn);

    // 3) Output projection: [16384,1024] @ [1024,1024] + b
    dim3 g3(DD / 128, BB * TT / 128);
    gemm_tc_kernel<<<g3, 256>>>(attn, w_out, b_out, out, BB * TT, DD, DD);
}

// round 9
// speedup vs baseline: 3.1888x; 1.1656x over previous
#include <cuda_runtime.h>
#include <cuda_bf16.h>
#include <cstdint>
#include <math.h>

#define BB 16
#define TT 1024
#define DD 1024
#define HH 16
#define HDD 64

// ---------------------------------------------------------------------------
// Scratch (allocation-free rule: __device__ globals)
// ---------------------------------------------------------------------------
__device__ __nv_bfloat16 g_xh[BB * TT * DD];        // X hi
__device__ __nv_bfloat16 g_xl[BB * TT * DD];        // X lo
__device__ __nv_bfloat16 g_wqkvT_h[3 * DD * DD];    // WqkvT [3D][D] hi
__device__ __nv_bfloat16 g_wqkvT_l[3 * DD * DD];
__device__ __nv_bfloat16 g_woutT_h[DD * DD];        // WoutT [D][D] hi
__device__ __nv_bfloat16 g_woutT_l[DD * DD];
__device__ __nv_bfloat16 g_qkvH[BB * TT * 3 * DD];  // qkv hi (Q pre-scaled)
__device__ __nv_bfloat16 g_qkvL[BB * TT * 3 * DD];  // qkv lo
__device__ __nv_bfloat16 g_attnH[BB * TT * DD];     // attention out hi
__device__ __nv_bfloat16 g_attnL[BB * TT * DD];     // attention out lo

// ---------------------------------------------------------------------------
// helpers
// ---------------------------------------------------------------------------
__device__ __forceinline__ unsigned ssa(const void* p) {
    return (unsigned)__cvta_generic_to_shared(p);
}
__device__ __forceinline__ void bf16split(float x, __nv_bfloat16& hi, __nv_bfloat16& lo) {
    hi = __float2bfloat16(x);
    lo = __float2bfloat16(x - __bfloat162float(hi));
}
__device__ __forceinline__ unsigned pack2(__nv_bfloat16 a, __nv_bfloat16 b) {
    __nv_bfloat162 v(a, b);
    return *reinterpret_cast<unsigned*>(&v);
}
__device__ __forceinline__ void ldsm4(unsigned& r0, unsigned& r1,
                                      unsigned& r2, unsigned& r3, unsigned a) {
    asm volatile("ldmatrix.sync.aligned.m8n8.x4.shared.b16 {%0,%1,%2,%3}, [%4];"
                 : "=r"(r0), "=r"(r1), "=r"(r2), "=r"(r3) : "r"(a));
}
__device__ __forceinline__ void ldsm4t(unsigned& r0, unsigned& r1,
                                       unsigned& r2, unsigned& r3, unsigned a) {
    asm volatile("ldmatrix.sync.aligned.m8n8.x4.trans.shared.b16 {%0,%1,%2,%3}, [%4];"
                 : "=r"(r0), "=r"(r1), "=r"(r2), "=r"(r3) : "r"(a));
}
__device__ __forceinline__ void mma16(float* c,
                                      unsigned a0, unsigned a1, unsigned a2, unsigned a3,
                                      unsigned b0, unsigned b1) {
    asm volatile(
        "mma.sync.aligned.m16n8k16.row.col.f32.bf16.bf16.f32 "
        "{%0,%1,%2,%3}, {%4,%5,%6,%7}, {%8,%9}, {%0,%1,%2,%3};"
        : "+f"(c[0]), "+f"(c[1]), "+f"(c[2]), "+f"(c[3])
        : "r"(a0), "r"(a1), "r"(a2), "r"(a3), "r"(b0), "r"(b1));
}
__device__ __forceinline__ void cpa16(uint32_t s, const void* g) {
    asm volatile("cp.async.cg.shared.global [%0], [%1], 16;" :: "r"(s), "l"(g));
}
#define CP_COMMIT() asm volatile("cp.async.commit_group;" ::: "memory")
#define CP_WAIT(n)  asm volatile("cp.async.wait_group %0;" :: "n"(n) : "memory")

#define SW128(off) ((off) ^ (((off) >> 3) & 0x70))

// ---------------------------------------------------------------------------
// Pre-pass 1: split fp32 -> bf16 hi/lo (elementwise, float4-vectorized)
// ---------------------------------------------------------------------------
__global__ void split_kernel(const float* __restrict__ X,
                             __nv_bfloat16* __restrict__ H,
                             __nv_bfloat16* __restrict__ L, int n4)
{
    int i = blockIdx.x * blockDim.x + threadIdx.x;
    if (i >= n4) return;
    float4 v = reinterpret_cast<const float4*>(X)[i];
    float f[4] = {v.x, v.y, v.z, v.w};
    __nv_bfloat16 h[4], l[4];
    #pragma unroll
    for (int j = 0; j < 4; j++) bf16split(f[j], h[j], l[j]);
    reinterpret_cast<uint2*>(H)[i] = make_uint2(pack2(h[0], h[1]), pack2(h[2], h[3]));
    reinterpret_cast<uint2*>(L)[i] = make_uint2(pack2(l[0], l[1]), pack2(l[2], l[3]));
}

// ---------------------------------------------------------------------------
// Pre-pass 2: W [K][N] fp32 -> WT [N][K] bf16 hi/lo (tiled transpose)
// ---------------------------------------------------------------------------
__global__ void transpose_split_kernel(const float* __restrict__ W,
                                       __nv_bfloat16* __restrict__ Th,
                                       __nv_bfloat16* __restrict__ Tl,
                                       int K, int N)
{
    __shared__ float t[32][33];
    int n0 = blockIdx.x * 32, k0 = blockIdx.y * 32;
    int tx = threadIdx.x, ty = threadIdx.y;
    #pragma unroll
    for (int i = 0; i < 32; i += 8)
        t[ty + i][tx] = W[(size_t)(k0 + ty + i) * N + n0 + tx];
    __syncthreads();
    #pragma unroll
    for (int i = 0; i < 32; i += 8) {
        float v = t[tx][ty + i];
        __nv_bfloat16 h, l;
        bf16split(v, h, l);
        Th[(size_t)(n0 + ty + i) * K + k0 + tx] = h;
        Tl[(size_t)(n0 + ty + i) * K + k0 + tx] = l;
    }
}

// ---------------------------------------------------------------------------
// bf16x2-split mma.sync GEMM, cp.async double-buffered, pure LDSM+MMA mainloop.
// C[M,N] = A[M,K] @ BT[N,K]^T + bias,  A/B pre-split bf16 hi/lo, B pre-transposed.
// Block 128x128, BK=32, 256 threads = 8 warps (4 row x 2 col), warp tile 32x64.
// Smem per stage: AH/AL/BH/BL each [128 rows][32 k] stride 40 bf16 (80B rows,
// conflict-free for ldmatrix: row*20 words mod 32 distinct over 8 rows).
// mode 0: fp32 out + bias.  mode 1: bf16 hi/lo out + bias, Q cols scaled 0.125.
// ---------------------------------------------------------------------------
__global__ void __launch_bounds__(256, 2)
gemm_mma_kernel(const __nv_bfloat16* __restrict__ Ah,
                const __nv_bfloat16* __restrict__ Al,
                const __nv_bfloat16* __restrict__ Bh,
                const __nv_bfloat16* __restrict__ Bl,
                const float* __restrict__ bias,
                float* __restrict__ Cf,
                __nv_bfloat16* __restrict__ Ch,
                __nv_bfloat16* __restrict__ Cl,
                int N, int K, int mode)
{
    extern __shared__ char dsm[];
    constexpr int STAGE = 40960;          // 4 arrays * 10240 B
    const uint32_t sb0 = ssa(dsm);

    const int tid = threadIdx.x;
    const int wid = tid >> 5;
    const int wr = wid & 3;
    const int wc = wid >> 2;
    const int lane = tid & 31;
    const int g = lane >> 2;
    const int t = lane & 3;
    const int lr  = lane & 7;
    const int tlo = (lane >> 3) & 1;
    const int thi = lane >> 4;
    const int blockRow = blockIdx.y * 128;
    const int blockCol = blockIdx.x * 128;
    const int NC = K / 32;

    float c[2][8][4];
    #pragma unroll
    for (int mf = 0; mf < 2; mf++)
        #pragma unroll
        for (int nf = 0; nf < 8; nf++)
            #pragma unroll
            for (int i = 0; i < 4; i++) c[mf][nf][i] = 0.f;

    auto load_chunk = [&](int cc) {
        const uint32_t sb = sb0 + (cc & 1) * STAGE;
        const int kt = cc * 32;
        #pragma unroll
        for (int i = 0; i < 2; i++) {
            int id = tid + i * 256;           // 0..511
            int row = id >> 2, u = id & 3;    // 128 rows x 4 x 16B
            uint32_t off = row * 80 + u * 16;
            size_t ga = (size_t)(blockRow + row) * K + kt + u * 8;
            size_t gb = (size_t)(blockCol + row) * K + kt + u * 8;
            cpa16(sb + off,         Ah + ga);
            cpa16(sb + 10240 + off, Al + ga);
            cpa16(sb + 20480 + off, Bh + gb);
            cpa16(sb + 30720 + off, Bl + gb);
        }
        CP_COMMIT();
    };

    load_chunk(0);
    if (NC > 1) load_chunk(1);

    for (int cc = 0; cc < NC; cc++) {
        if (cc + 1 < NC) CP_WAIT(1); else CP_WAIT(0);
        __syncthreads();

        const uint32_t sb = sb0 + (cc & 1) * STAGE;
        #pragma unroll
        for (int ks = 0; ks < 2; ks++) {
            unsigned ah[2][4], al_[2][4];
            #pragma unroll
            for (int mf = 0; mf < 2; mf++) {
                int row = wr * 32 + mf * 16 + tlo * 8 + lr;
                uint32_t off = row * 80 + ks * 32 + thi * 16;
                ldsm4(ah[mf][0], ah[mf][1], ah[mf][2], ah[mf][3], sb + off);
                ldsm4(al_[mf][0], al_[mf][1], al_[mf][2], al_[mf][3], sb + 10240 + off);
            }
            #pragma unroll
            for (int np = 0; np < 4; np++) {
                int nrow = wc * 64 + np * 16 + thi * 8 + lr;
                uint32_t off = nrow * 80 + ks * 32 + tlo * 16;
                unsigned bh[4], bl[4];
                ldsm4(bh[0], bh[1], bh[2], bh[3], sb + 20480 + off);
                ldsm4(bl[0], bl[1], bl[2], bl[3], sb + 30720 + off);
                #pragma unroll
                for (int half = 0; half < 2; half++) {
                    int nf = np * 2 + half;
                    unsigned b0h = bh[2 * half], b1h = bh[2 * half + 1];
                    unsigned b0l = bl[2 * half], b1l = bl[2 * half + 1];
                    #pragma unroll
                    for (int mf = 0; mf < 2; mf++) {
                        mma16(c[mf][nf], ah[mf][0], ah[mf][1], ah[mf][2], ah[mf][3], b0h, b1h);
                        mma16(c[mf][nf], ah[mf][0], ah[mf][1], ah[mf][2], ah[mf][3], b0l, b1l);
                        mma16(c[mf][nf], al_[mf][0], al_[mf][1], al_[mf][2], al_[mf][3], b0h, b1h);
                    }
                }
            }
        }
        __syncthreads();
        if (cc + 2 < NC) load_chunk(cc + 2);
    }

    // epilogue
    const float qs = (mode == 1 && blockCol < DD) ? 0.125f : 1.0f;
    #pragma unroll
    for (int mf = 0; mf < 2; mf++) {
        int row = blockRow + wr * 32 + mf * 16 + g;
        #pragma unroll
        for (int nf = 0; nf < 8; nf++) {
            int col = blockCol + wc * 64 + nf * 8 + 2 * t;
            float bx = bias[col], by = bias[col + 1];
            float v0 = (c[mf][nf][0] + bx) * qs;
            float v1 = (c[mf][nf][1] + by) * qs;
            float v2 = (c[mf][nf][2] + bx) * qs;
            float v3 = (c[mf][nf][3] + by) * qs;
            if (mode == 0) {
                *reinterpret_cast<float2*>(&Cf[(size_t)row * N + col]) = make_float2(v0, v1);
                *reinterpret_cast<float2*>(&Cf[(size_t)(row + 8) * N + col]) = make_float2(v2, v3);
            } else {
                __nv_bfloat16 h0, l0, h1, l1;
                bf16split(v0, h0, l0); bf16split(v1, h1, l1);
                *reinterpret_cast<unsigned*>(&Ch[(size_t)row * N + col]) = pack2(h0, h1);
                *reinterpret_cast<unsigned*>(&Cl[(size_t)row * N + col]) = pack2(l0, l1);
                bf16split(v2, h0, l0); bf16split(v3, h1, l1);
                *reinterpret_cast<unsigned*>(&Ch[(size_t)(row + 8) * N + col]) = pack2(h0, h1);
                *reinterpret_cast<unsigned*>(&Cl[(size_t)(row + 8) * N + col]) = pack2(l0, l1);
            }
        }
    }
}

// ---------------------------------------------------------------------------
// Flash attention, bf16 3-term split, inputs pre-split bf16 (Q pre-scaled).
// Block = 64 q rows of one (b,h); 128 threads = 4 warps.
// Smem: QH QL KH KL VH VL, each [64][64] bf16 SW128-swizzled (8 KB) = 48 KB.
// Mainloop: cp.async tile loads -> ldmatrix -> mma; P stays in registers.
// ---------------------------------------------------------------------------
__global__ void __launch_bounds__(128, 4)
attn_tc_kernel(const __nv_bfloat16* __restrict__ qh,
               const __nv_bfloat16* __restrict__ ql,
               __nv_bfloat16* __restrict__ outH,
               __nv_bfloat16* __restrict__ outL)
{
    extern __shared__ char asm_[];
    const uint32_t QHs = ssa(asm_);
    const uint32_t QLs = QHs + 8192;
    const uint32_t KHs = QHs + 16384;
    const uint32_t KLs = QHs + 24576;
    const uint32_t VHs = QHs + 32768;
    const uint32_t VLs = QHs + 40960;

    const int b = blockIdx.z;
    const int h = blockIdx.y;
    const int qt = blockIdx.x;
    const int tid = threadIdx.x;
    const int w = tid >> 5;
    const int lane = tid & 31;
    const int g = lane >> 2;
    const int t = lane & 3;
    const int lr  = lane & 7;
    const int tlo = (lane >> 3) & 1;
    const int thi = lane >> 4;
    const int t0 = qt * 64;

    const size_t rowstride = 3 * DD;
    const size_t base = (size_t)(b * TT) * rowstride + h * HDD;

    // Q tile load (8 cp.async per thread per array-pair)
    {
        #pragma unroll
        for (int i = 0; i < 4; i++) {
            int id = tid + i * 128;                 // 0..511
            int r = id >> 3, u = id & 7;
            uint32_t so = SW128(r * 128 + u * 16);
            size_t go = base + (size_t)(t0 + r) * rowstride + u * 8;
            cpa16(QHs + so, qh + go);
            cpa16(QLs + so, ql + go);
        }
    }

    float o[8][4];
    #pragma unroll
    for (int nf = 0; nf < 8; nf++)
        #pragma unroll
        for (int i = 0; i < 4; i++) o[nf][i] = 0.f;
    float m[2] = {-1e30f, -1e30f};
    float l2s[2] = {0.f, 0.f};

    for (int kt = 0; kt < TT / 64; kt++) {
        // K/V tile loads (16 cp.async per thread)
        #pragma unroll
        for (int i = 0; i < 8; i++) {
            int id = tid + i * 128;                 // 0..1023
            int r = (id >> 3) & 63, u = id & 7;
            int kv = id >> 9;                       // 0 = K, 1 = V
            uint32_t so = SW128(r * 128 + u * 16);
            size_t go = base + DD + (size_t)kv * DD
                      + (size_t)(kt * 64 + r) * rowstride + u * 8;
            cpa16((kv ? VHs : KHs) + so, qh + go);
            cpa16((kv ? VLs : KLs) + so, ql + go);
        }
        CP_COMMIT();
        CP_WAIT(0);
        __syncthreads();

        // ---- S = Q @ K^T ----
        float sc[8][4];
        #pragma unroll
        for (int nf = 0; nf < 8; nf++)
            #pragma unroll
            for (int i = 0; i < 4; i++) sc[nf][i] = 0.f;

        #pragma unroll
        for (int ks = 0; ks < 4; ks++) {
            unsigned qfh[4], qfl[4];
            {
                int row = 16 * w + tlo * 8 + lr;
                uint32_t so = SW128(row * 128 + ks * 32 + thi * 16);
                ldsm4(qfh[0], qfh[1], qfh[2], qfh[3], QHs + so);
                ldsm4(qfl[0], qfl[1], qfl[2], qfl[3], QLs + so);
            }
            #pragma unroll
            for (int np = 0; np < 4; np++) {
                int row = np * 16 + thi * 8 + lr;
                uint32_t so = SW128(row * 128 + ks * 32 + tlo * 16);
                unsigned kh[4], kl[4];
                ldsm4(kh[0], kh[1], kh[2], kh[3], KHs + so);
                ldsm4(kl[0], kl[1], kl[2], kl[3], KLs + so);
                #pragma unroll
                for (int half = 0; half < 2; half++) {
                    int nf = np * 2 + half;
                    unsigned b0h = kh[2 * half], b1h = kh[2 * half + 1];
                    unsigned b0l = kl[2 * half], b1l = kl[2 * half + 1];
                    mma16(sc[nf], qfh[0], qfh[1], qfh[2], qfh[3], b0h, b1h);
                    mma16(sc[nf], qfh[0], qfh[1], qfh[2], qfh[3], b0l, b1l);
                    mma16(sc[nf], qfl[0], qfl[1], qfl[2], qfl[3], b0h, b1h);
                }
            }
        }

        // ---- online softmax ----
        #pragma unroll
        for (int r = 0; r < 2; r++) {
            float mx = -1e30f;
            #pragma unroll
            for (int nf = 0; nf < 8; nf++)
                mx = fmaxf(mx, fmaxf(sc[nf][2 * r], sc[nf][2 * r + 1]));
            mx = fmaxf(mx, __shfl_xor_sync(0xffffffffu, mx, 1));
            mx = fmaxf(mx, __shfl_xor_sync(0xffffffffu, mx, 2));
            float mn = fmaxf(m[r], mx);
            float alpha = __expf(m[r] - mn);
            m[r] = mn;
            float sum = 0.f;
            #pragma unroll
            for (int nf = 0; nf < 8; nf++) {
                float p0 = __expf(sc[nf][2 * r] - mn);
                float p1 = __expf(sc[nf][2 * r + 1] - mn);
                sc[nf][2 * r] = p0;
                sc[nf][2 * r + 1] = p1;
                sum += p0 + p1;
            }
            sum += __shfl_xor_sync(0xffffffffu, sum, 1);
            sum += __shfl_xor_sync(0xffffffffu, sum, 2);
            l2s[r] = l2s[r] * alpha + sum;
            #pragma unroll
            for (int nf = 0; nf < 8; nf++) {
                o[nf][2 * r] *= alpha;
                o[nf][2 * r + 1] *= alpha;
            }
        }

        // ---- O += P @ V ----
        #pragma unroll
        for (int ks2 = 0; ks2 < 4; ks2++) {
            unsigned pa_h[4], pa_l[4];
            #pragma unroll
            for (int half = 0; half < 2; half++) {
                const float* s4 = sc[2 * ks2 + half];
                __nv_bfloat16 h0, l0, h1, l1, h2, l2, h3, l3;
                bf16split(s4[0], h0, l0);
                bf16split(s4[1], h1, l1);
                bf16split(s4[2], h2, l2);
                bf16split(s4[3], h3, l3);
                pa_h[2 * half]     = pack2(h0, h1);
                pa_h[2 * half + 1] = pack2(h2, h3);
                pa_l[2 * half]     = pack2(l0, l1);
                pa_l[2 * half + 1] = pack2(l2, l3);
            }
            #pragma unroll
            for (int np = 0; np < 4; np++) {
                int vr = ks2 * 16 + tlo * 8 + lr;
                uint32_t so = SW128(vr * 128 + np * 32 + thi * 16);
                unsigned vh[4], vl[4];
                ldsm4t(vh[0], vh[1], vh[2], vh[3], VHs + so);
                ldsm4t(vl[0], vl[1], vl[2], vl[3], VLs + so);
                #pragma unroll
                for (int half = 0; half < 2; half++) {
                    int nfo = np * 2 + half;
                    unsigned b0h = vh[2 * half], b1h = vh[2 * half + 1];
                    unsigned b0l = vl[2 * half], b1l = vl[2 * half + 1];
                    mma16(o[nfo], pa_h[0], pa_h[1], pa_h[2], pa_h[3], b0h, b1h);
                    mma16(o[nfo], pa_h[0], pa_h[1], pa_h[2], pa_h[3], b0l, b1l);
                    mma16(o[nfo], pa_l[0], pa_l[1], pa_l[2], pa_l[3], b0h, b1h);
                }
            }
        }
        __syncthreads();   // all reads of K/V done before next tile's cp.async
    }

    // normalize + write bf16 hi/lo
    #pragma unroll
    for (int r = 0; r < 2; r++) {
        float inv = 1.f / l2s[r];
        int row = t0 + 16 * w + g + 8 * r;
        #pragma unroll
        for (int nf = 0; nf < 8; nf++) {
            int col = h * HDD + nf * 8 + 2 * t;
            float v0 = o[nf][2 * r] * inv;
            float v1 = o[nf][2 * r + 1] * inv;
            __nv_bfloat16 h0, l0, h1, l1;
            bf16split(v0, h0, l0);
            bf16split(v1, h1, l1);
            size_t idx = (size_t)(b * TT + row) * DD + col;
            *reinterpret_cast<unsigned*>(&outH[idx]) = pack2(h0, h1);
            *reinterpret_cast<unsigned*>(&outL[idx]) = pack2(l0, l1);
        }
    }
}

// ---------------------------------------------------------------------------
extern "C" void kernel_launch(void* const* d_in, const int* in_sizes, int n_in,
                              void* d_out, int out_size)
{
    const float* x     = (const float*)d_in[0];
    const float* w_qkv = (const float*)d_in[1];
    const float* b_qkv = (const float*)d_in[2];
    const float* w_out = (const float*)d_in[3];
    const float* b_out = (const float*)d_in[4];
    float* out = (float*)d_out;

    __nv_bfloat16 *xh, *xl, *wqh, *wql, *woh, *wol, *qkvh, *qkvl, *ah, *al;
    cudaGetSymbolAddress((void**)&xh,   g_xh);
    cudaGetSymbolAddress((void**)&xl,   g_xl);
    cudaGetSymbolAddress((void**)&wqh,  g_wqkvT_h);
    cudaGetSymbolAddress((void**)&wql,  g_wqkvT_l);
    cudaGetSymbolAddress((void**)&woh,  g_woutT_h);
    cudaGetSymbolAddress((void**)&wol,  g_woutT_l);
    cudaGetSymbolAddress((void**)&qkvh, g_qkvH);
    cudaGetSymbolAddress((void**)&qkvl, g_qkvL);
    cudaGetSymbolAddress((void**)&ah,   g_attnH);
    cudaGetSymbolAddress((void**)&al,   g_attnL);

    const int GEMM_SMEM = 2 * 40960;   // 80 KB
    cudaFuncSetAttribute(gemm_mma_kernel,
                         cudaFuncAttributeMaxDynamicSharedMemorySize, GEMM_SMEM);
    const int ATTN_SMEM = 6 * 8192;    // 48 KB
    cudaFuncSetAttribute(attn_tc_kernel,
                         cudaFuncAttributeMaxDynamicSharedMemorySize, ATTN_SMEM);

    // Pre-pass: split X; transpose+split weights
    {
        int n4 = BB * TT * DD / 4;
        split_kernel<<<(n4 + 255) / 256, 256>>>(x, xh, xl, n4);
        dim3 bt(32, 8);
        transpose_split_kernel<<<dim3(3 * DD / 32, DD / 32), bt>>>(w_qkv, wqh, wql, DD, 3 * DD);
        transpose_split_kernel<<<dim3(DD / 32, DD / 32), bt>>>(w_out, woh, wol, DD, DD);
    }

    // 1) QKV projection -> bf16 hi/lo (Q pre-scaled by 0.125)
    gemm_mma_kernel<<<dim3(3 * DD / 128, BB * TT / 128), 256, GEMM_SMEM>>>(
        xh, xl, wqh, wql, b_qkv, nullptr, qkvh, qkvl, 3 * DD, DD, 1);

    // 2) Attention -> bf16 hi/lo
    attn_tc_kernel<<<dim3(TT / 64, HH, BB), 128, ATTN_SMEM>>>(qkvh, qkvl, ah, al);

    // 3) Output projection -> fp32 d_out
    gemm_mma_kernel<<<dim3(DD / 128, BB * TT / 128), 256, GEMM_SMEM>>>(
        ah, al, woh, wol, b_out, out, nullptr, nullptr, DD, DD, 0);
}

// round 12
// speedup vs baseline: 3.5001x; 1.0976x over previous
#include <cuda_runtime.h>
#include <cuda_bf16.h>
#include <cstdint>
#include <math.h>

#define BB 16
#define TT 1024
#define DD 1024
#define HH 16
#define HDD 64

// ---------------------------------------------------------------------------
// Scratch (allocation-free rule: __device__ globals)
// ---------------------------------------------------------------------------
__device__ __nv_bfloat16 g_xh[BB * TT * DD];        // X hi
__device__ __nv_bfloat16 g_xl[BB * TT * DD];        // X lo
__device__ __nv_bfloat16 g_wqkvT_h[3 * DD * DD];    // WqkvT [3D][D] hi
__device__ __nv_bfloat16 g_wqkvT_l[3 * DD * DD];
__device__ __nv_bfloat16 g_woutT_h[DD * DD];        // WoutT [D][D] hi
__device__ __nv_bfloat16 g_woutT_l[DD * DD];
__device__ __nv_bfloat16 g_qkvH[BB * TT * 3 * DD];  // qkv hi (Q pre-scaled)
__device__ __nv_bfloat16 g_qkvL[BB * TT * 3 * DD];  // qkv lo
__device__ __nv_bfloat16 g_attnH[BB * TT * DD];     // attention out hi
__device__ __nv_bfloat16 g_attnL[BB * TT * DD];     // attention out lo

// ---------------------------------------------------------------------------
// helpers
// ---------------------------------------------------------------------------
__device__ __forceinline__ unsigned ssa(const void* p) {
    return (unsigned)__cvta_generic_to_shared(p);
}
__device__ __forceinline__ void bf16split(float x, __nv_bfloat16& hi, __nv_bfloat16& lo) {
    hi = __float2bfloat16(x);
    lo = __float2bfloat16(x - __bfloat162float(hi));
}
__device__ __forceinline__ unsigned pack2(__nv_bfloat16 a, __nv_bfloat16 b) {
    __nv_bfloat162 v(a, b);
    return *reinterpret_cast<unsigned*>(&v);
}
__device__ __forceinline__ void ldsm4(unsigned& r0, unsigned& r1,
                                      unsigned& r2, unsigned& r3, unsigned a) {
    asm volatile("ldmatrix.sync.aligned.m8n8.x4.shared.b16 {%0,%1,%2,%3}, [%4];"
                 : "=r"(r0), "=r"(r1), "=r"(r2), "=r"(r3) : "r"(a));
}
__device__ __forceinline__ void ldsm4t(unsigned& r0, unsigned& r1,
                                       unsigned& r2, unsigned& r3, unsigned a) {
    asm volatile("ldmatrix.sync.aligned.m8n8.x4.trans.shared.b16 {%0,%1,%2,%3}, [%4];"
                 : "=r"(r0), "=r"(r1), "=r"(r2), "=r"(r3) : "r"(a));
}
__device__ __forceinline__ void mma16(float* c,
                                      unsigned a0, unsigned a1, unsigned a2, unsigned a3,
                                      unsigned b0, unsigned b1) {
    asm volatile(
        "mma.sync.aligned.m16n8k16.row.col.f32.bf16.bf16.f32 "
        "{%0,%1,%2,%3}, {%4,%5,%6,%7}, {%8,%9}, {%0,%1,%2,%3};"
        : "+f"(c[0]), "+f"(c[1]), "+f"(c[2]), "+f"(c[3])
        : "r"(a0), "r"(a1), "r"(a2), "r"(a3), "r"(b0), "r"(b1));
}
__device__ __forceinline__ void cpa16(uint32_t s, const void* g) {
    asm volatile("cp.async.cg.shared.global [%0], [%1], 16;" :: "r"(s), "l"(g));
}
#define CP_COMMIT() asm volatile("cp.async.commit_group;" ::: "memory")
#define CP_WAIT(n)  asm volatile("cp.async.wait_group %0;" :: "n"(n) : "memory")

#define SW128(off) ((off) ^ (((off) >> 3) & 0x70))
#define SW64B(off) ((off) ^ (((off) >> 3) & 0x30))

// ---------------------------------------------------------------------------
// Pre-pass 1: split fp32 -> bf16 hi/lo
// ---------------------------------------------------------------------------
__global__ void split_kernel(const float* __restrict__ X,
                             __nv_bfloat16* __restrict__ H,
                             __nv_bfloat16* __restrict__ L, int n4)
{
    int i = blockIdx.x * blockDim.x + threadIdx.x;
    if (i >= n4) return;
    float4 v = reinterpret_cast<const float4*>(X)[i];
    float f[4] = {v.x, v.y, v.z, v.w};
    __nv_bfloat16 h[4], l[4];
    #pragma unroll
    for (int j = 0; j < 4; j++) bf16split(f[j], h[j], l[j]);
    reinterpret_cast<uint2*>(H)[i] = make_uint2(pack2(h[0], h[1]), pack2(h[2], h[3]));
    reinterpret_cast<uint2*>(L)[i] = make_uint2(pack2(l[0], l[1]), pack2(l[2], l[3]));
}

// ---------------------------------------------------------------------------
// Pre-pass 2: W [K][N] fp32 -> WT [N][K] bf16 hi/lo
// ---------------------------------------------------------------------------
__global__ void transpose_split_kernel(const float* __restrict__ W,
                                       __nv_bfloat16* __restrict__ Th,
                                       __nv_bfloat16* __restrict__ Tl,
                                       int K, int N)
{
    __shared__ float t[32][33];
    int n0 = blockIdx.x * 32, k0 = blockIdx.y * 32;
    int tx = threadIdx.x, ty = threadIdx.y;
    #pragma unroll
    for (int i = 0; i < 32; i += 8)
        t[ty + i][tx] = W[(size_t)(k0 + ty + i) * N + n0 + tx];
    __syncthreads();
    #pragma unroll
    for (int i = 0; i < 32; i += 8) {
        float v = t[tx][ty + i];
        __nv_bfloat16 h, l;
        bf16split(v, h, l);
        Th[(size_t)(n0 + ty + i) * K + k0 + tx] = h;
        Tl[(size_t)(n0 + ty + i) * K + k0 + tx] = l;
    }
}

// ---------------------------------------------------------------------------
// bf16x2-split mma.sync GEMM, 3-stage cp.async pipeline, SW64-swizzled tiles.
// C[M,N] = A[M,K] @ BT[N,K]^T + bias.  Block 128x128, BK=32, 256 thr = 8 warps.
// Stage (32 KB): AH[128x64B] AL BH BL; SW64 swizzle -> ldmatrix conflict-free.
// mode 0: fp32 out + bias.  mode 1: bf16 hi/lo out + bias, Q cols scaled 0.125.
// ---------------------------------------------------------------------------
__global__ void __launch_bounds__(256, 2)
gemm_mma_kernel(const __nv_bfloat16* __restrict__ Ah,
                const __nv_bfloat16* __restrict__ Al,
                const __nv_bfloat16* __restrict__ Bh,
                const __nv_bfloat16* __restrict__ Bl,
                const float* __restrict__ bias,
                float* __restrict__ Cf,
                __nv_bfloat16* __restrict__ Ch,
                __nv_bfloat16* __restrict__ Cl,
                int N, int K, int mode)
{
    extern __shared__ char dsm[];
    constexpr int STAGE = 32768;          // 4 arrays * 8192 B
    const uint32_t sb0 = ssa(dsm);

    const int tid = threadIdx.x;
    const int wid = tid >> 5;
    const int wr = wid & 3;
    const int wc = wid >> 2;
    const int lane = tid & 31;
    const int g = lane >> 2;
    const int t = lane & 3;
    const int lr  = lane & 7;
    const int tlo = (lane >> 3) & 1;
    const int thi = lane >> 4;
    const int blockRow = blockIdx.y * 128;
    const int blockCol = blockIdx.x * 128;
    const int NC = K / 32;                // 32 chunks

    float c[2][8][4];
    #pragma unroll
    for (int mf = 0; mf < 2; mf++)
        #pragma unroll
        for (int nf = 0; nf < 8; nf++)
            #pragma unroll
            for (int i = 0; i < 4; i++) c[mf][nf][i] = 0.f;

    auto load_chunk = [&](int cc) {
        const uint32_t sb = sb0 + (cc % 3) * STAGE;
        const int kt = cc * 32;
        #pragma unroll
        for (int i = 0; i < 2; i++) {
            int id = tid + i * 256;           // 0..511
            int row = id >> 2, u = id & 3;    // 128 rows x 4 x 16B
            uint32_t off = SW64B(row * 64 + u * 16);
            size_t ga = (size_t)(blockRow + row) * K + kt + u * 8;
            size_t gb = (size_t)(blockCol + row) * K + kt + u * 8;
            cpa16(sb + off,         Ah + ga);
            cpa16(sb +  8192 + off, Al + ga);
            cpa16(sb + 16384 + off, Bh + gb);
            cpa16(sb + 24576 + off, Bl + gb);
        }
        CP_COMMIT();
    };

    load_chunk(0);
    load_chunk(1);
    load_chunk(2);

    for (int cc = 0; cc < NC; cc++) {
        if (cc + 2 < NC)      CP_WAIT(2);
        else if (cc + 1 < NC) CP_WAIT(1);
        else                  CP_WAIT(0);
        __syncthreads();

        const uint32_t sb = sb0 + (cc % 3) * STAGE;
        #pragma unroll
        for (int ks = 0; ks < 2; ks++) {
            unsigned ah[2][4], al_[2][4];
            #pragma unroll
            for (int mf = 0; mf < 2; mf++) {
                int row = wr * 32 + mf * 16 + tlo * 8 + lr;
                uint32_t off = SW64B(row * 64 + ks * 32 + thi * 16);
                ldsm4(ah[mf][0], ah[mf][1], ah[mf][2], ah[mf][3], sb + off);
                ldsm4(al_[mf][0], al_[mf][1], al_[mf][2], al_[mf][3], sb + 8192 + off);
            }
            #pragma unroll
            for (int np = 0; np < 4; np++) {
                int nrow = wc * 64 + np * 16 + thi * 8 + lr;
                uint32_t off = SW64B(nrow * 64 + ks * 32 + tlo * 16);
                unsigned bh[4], bl[4];
                ldsm4(bh[0], bh[1], bh[2], bh[3], sb + 16384 + off);
                ldsm4(bl[0], bl[1], bl[2], bl[3], sb + 24576 + off);
                #pragma unroll
                for (int half = 0; half < 2; half++) {
                    int nf = np * 2 + half;
                    unsigned b0h = bh[2 * half], b1h = bh[2 * half + 1];
                    unsigned b0l = bl[2 * half], b1l = bl[2 * half + 1];
                    #pragma unroll
                    for (int mf = 0; mf < 2; mf++) {
                        mma16(c[mf][nf], ah[mf][0], ah[mf][1], ah[mf][2], ah[mf][3], b0h, b1h);
                        mma16(c[mf][nf], ah[mf][0], ah[mf][1], ah[mf][2], ah[mf][3], b0l, b1l);
                        mma16(c[mf][nf], al_[mf][0], al_[mf][1], al_[mf][2], al_[mf][3], b0h, b1h);
                    }
                }
            }
        }
        __syncthreads();
        if (cc + 3 < NC) load_chunk(cc + 3);
    }

    // epilogue
    const float qs = (mode == 1 && blockCol < DD) ? 0.125f : 1.0f;
    #pragma unroll
    for (int mf = 0; mf < 2; mf++) {
        int row = blockRow + wr * 32 + mf * 16 + g;
        #pragma unroll
        for (int nf = 0; nf < 8; nf++) {
            int col = blockCol + wc * 64 + nf * 8 + 2 * t;
            float bx = bias[col], by = bias[col + 1];
            float v0 = (c[mf][nf][0] + bx) * qs;
            float v1 = (c[mf][nf][1] + by) * qs;
            float v2 = (c[mf][nf][2] + bx) * qs;
            float v3 = (c[mf][nf][3] + by) * qs;
            if (mode == 0) {
                *reinterpret_cast<float2*>(&Cf[(size_t)row * N + col]) = make_float2(v0, v1);
                *reinterpret_cast<float2*>(&Cf[(size_t)(row + 8) * N + col]) = make_float2(v2, v3);
            } else {
                __nv_bfloat16 h0, l0, h1, l1;
                bf16split(v0, h0, l0); bf16split(v1, h1, l1);
                *reinterpret_cast<unsigned*>(&Ch[(size_t)row * N + col]) = pack2(h0, h1);
                *reinterpret_cast<unsigned*>(&Cl[(size_t)row * N + col]) = pack2(l0, l1);
                bf16split(v2, h0, l0); bf16split(v3, h1, l1);
                *reinterpret_cast<unsigned*>(&Ch[(size_t)(row + 8) * N + col]) = pack2(h0, h1);
                *reinterpret_cast<unsigned*>(&Cl[(size_t)(row + 8) * N + col]) = pack2(l0, l1);
            }
        }
    }
}

// ---------------------------------------------------------------------------
// Flash attention, bf16 3-term split, split K/V commit groups for overlap:
// wait K -> S -> sync -> issue K(kt+1) -> softmax -> wait V -> PV -> issue V(kt+1).
// Block = 64 q rows of one (b,h); 128 threads = 4 warps; 48 KB smem, 4 CTAs/SM.
// ---------------------------------------------------------------------------
__global__ void __launch_bounds__(128, 4)
attn_tc_kernel(const __nv_bfloat16* __restrict__ qh,
               const __nv_bfloat16* __restrict__ ql,
               __nv_bfloat16* __restrict__ outH,
               __nv_bfloat16* __restrict__ outL)
{
    extern __shared__ char asm_[];
    const uint32_t QHs = ssa(asm_);
    const uint32_t QLs = QHs + 8192;
    const uint32_t KHs = QHs + 16384;
    const uint32_t KLs = QHs + 24576;
    const uint32_t VHs = QHs + 32768;
    const uint32_t VLs = QHs + 40960;

    const int b = blockIdx.z;
    const int h = blockIdx.y;
    const int qt = blockIdx.x;
    const int tid = threadIdx.x;
    const int w = tid >> 5;
    const int lane = tid & 31;
    const int g = lane >> 2;
    const int t = lane & 3;
    const int lr  = lane & 7;
    const int tlo = (lane >> 3) & 1;
    const int thi = lane >> 4;
    const int t0 = qt * 64;
    const int NT = TT / 64;

    const size_t rowstride = 3 * DD;
    const size_t base = (size_t)(b * TT) * rowstride + h * HDD;

    auto load_k = [&](int kt) {
        #pragma unroll
        for (int i = 0; i < 4; i++) {
            int id = tid + i * 128;                 // 0..511
            int r = id >> 3, u = id & 7;
            uint32_t so = SW128(r * 128 + u * 16);
            size_t go = base + DD + (size_t)(kt * 64 + r) * rowstride + u * 8;
            cpa16(KHs + so, qh + go);
            cpa16(KLs + so, ql + go);
        }
        CP_COMMIT();
    };
    auto load_v = [&](int kt) {
        #pragma unroll
        for (int i = 0; i < 4; i++) {
            int id = tid + i * 128;
            int r = id >> 3, u = id & 7;
            uint32_t so = SW128(r * 128 + u * 16);
            size_t go = base + 2 * DD + (size_t)(kt * 64 + r) * rowstride + u * 8;
            cpa16(VHs + so, qh + go);
            cpa16(VLs + so, ql + go);
        }
        CP_COMMIT();
    };

    // Q tile load (own commit group), then K0, V0
    {
        #pragma unroll
        for (int i = 0; i < 4; i++) {
            int id = tid + i * 128;
            int r = id >> 3, u = id & 7;
            uint32_t so = SW128(r * 128 + u * 16);
            size_t go = base + (size_t)(t0 + r) * rowstride + u * 8;
            cpa16(QHs + so, qh + go);
            cpa16(QLs + so, ql + go);
        }
        CP_COMMIT();
    }
    load_k(0);
    load_v(0);

    float o[8][4];
    #pragma unroll
    for (int nf = 0; nf < 8; nf++)
        #pragma unroll
        for (int i = 0; i < 4; i++) o[nf][i] = 0.f;
    float m[2] = {-1e30f, -1e30f};
    float l2s[2] = {0.f, 0.f};

    for (int kt = 0; kt < NT; kt++) {
        // wait for K(kt) (V(kt) may still be in flight)
        CP_WAIT(1);
        __syncthreads();

        // ---- S = Q @ K^T ----
        float sc[8][4];
        #pragma unroll
        for (int nf = 0; nf < 8; nf++)
            #pragma unroll
            for (int i = 0; i < 4; i++) sc[nf][i] = 0.f;

        #pragma unroll
        for (int ks = 0; ks < 4; ks++) {
            unsigned qfh[4], qfl[4];
            {
                int row = 16 * w + tlo * 8 + lr;
                uint32_t so = SW128(row * 128 + ks * 32 + thi * 16);
                ldsm4(qfh[0], qfh[1], qfh[2], qfh[3], QHs + so);
                ldsm4(qfl[0], qfl[1], qfl[2], qfl[3], QLs + so);
            }
            #pragma unroll
            for (int np = 0; np < 4; np++) {
                int row = np * 16 + thi * 8 + lr;
                uint32_t so = SW128(row * 128 + ks * 32 + tlo * 16);
                unsigned kh[4], kl[4];
                ldsm4(kh[0], kh[1], kh[2], kh[3], KHs + so);
                ldsm4(kl[0], kl[1], kl[2], kl[3], KLs + so);
                #pragma unroll
                for (int half = 0; half < 2; half++) {
                    int nf = np * 2 + half;
                    unsigned b0h = kh[2 * half], b1h = kh[2 * half + 1];
                    unsigned b0l = kl[2 * half], b1l = kl[2 * half + 1];
                    mma16(sc[nf], qfh[0], qfh[1], qfh[2], qfh[3], b0h, b1h);
                    mma16(sc[nf], qfh[0], qfh[1], qfh[2], qfh[3], b0l, b1l);
                    mma16(sc[nf], qfl[0], qfl[1], qfl[2], qfl[3], b0h, b1h);
                }
            }
        }

        __syncthreads();                 // all warps done reading K buffer
        if (kt + 1 < NT) load_k(kt + 1); // K(kt+1) hides behind softmax + PV

        // ---- online softmax (registers only) ----
        #pragma unroll
        for (int r = 0; r < 2; r++) {
            float mx = -1e30f;
            #pragma unroll
            for (int nf = 0; nf < 8; nf++)
                mx = fmaxf(mx, fmaxf(sc[nf][2 * r], sc[nf][2 * r + 1]));
            mx = fmaxf(mx, __shfl_xor_sync(0xffffffffu, mx, 1));
            mx = fmaxf(mx, __shfl_xor_sync(0xffffffffu, mx, 2));
            float mn = fmaxf(m[r], mx);
            float alpha = __expf(m[r] - mn);
            m[r] = mn;
            float sum = 0.f;
            #pragma unroll
            for (int nf = 0; nf < 8; nf++) {
                float p0 = __expf(sc[nf][2 * r] - mn);
                float p1 = __expf(sc[nf][2 * r + 1] - mn);
                sc[nf][2 * r] = p0;
                sc[nf][2 * r + 1] = p1;
                sum += p0 + p1;
            }
            sum += __shfl_xor_sync(0xffffffffu, sum, 1);
            sum += __shfl_xor_sync(0xffffffffu, sum, 2);
            l2s[r] = l2s[r] * alpha + sum;
            #pragma unroll
            for (int nf = 0; nf < 8; nf++) {
                o[nf][2 * r] *= alpha;
                o[nf][2 * r + 1] *= alpha;
            }
        }

        // wait for V(kt); one group (K(kt+1)) may remain outstanding
        if (kt + 1 < NT) CP_WAIT(1); else CP_WAIT(0);
        __syncthreads();

        // ---- O += P @ V ----
        #pragma unroll
        for (int ks2 = 0; ks2 < 4; ks2++) {
            unsigned pa_h[4], pa_l[4];
            #pragma unroll
            for (int half = 0; half < 2; half++) {
                const float* s4 = sc[2 * ks2 + half];
                __nv_bfloat16 h0, l0, h1, l1, h2, l2, h3, l3;
                bf16split(s4[0], h0, l0);
                bf16split(s4[1], h1, l1);
                bf16split(s4[2], h2, l2);
                bf16split(s4[3], h3, l3);
                pa_h[2 * half]     = pack2(h0, h1);
                pa_h[2 * half + 1] = pack2(h2, h3);
                pa_l[2 * half]     = pack2(l0, l1);
                pa_l[2 * half + 1] = pack2(l2, l3);
            }
            #pragma unroll
            for (int np = 0; np < 4; np++) {
                int vr = ks2 * 16 + tlo * 8 + lr;
                uint32_t so = SW128(vr * 128 + np * 32 + thi * 16);
                unsigned vh[4], vl[4];
                ldsm4t(vh[0], vh[1], vh[2], vh[3], VHs + so);
                ldsm4t(vl[0], vl[1], vl[2], vl[3], VLs + so);
                #pragma unroll
                for (int half = 0; half < 2; half++) {
                    int nfo = np * 2 + half;
                    unsigned b0h = vh[2 * half], b1h = vh[2 * half + 1];
                    unsigned b0l = vl[2 * half], b1l = vl[2 * half + 1];
                    mma16(o[nfo], pa_h[0], pa_h[1], pa_h[2], pa_h[3], b0h, b1h);
                    mma16(o[nfo], pa_h[0], pa_h[1], pa_h[2], pa_h[3], b0l, b1l);
                    mma16(o[nfo], pa_l[0], pa_l[1], pa_l[2], pa_l[3], b0h, b1h);
                }
            }
        }

        __syncthreads();                 // all warps done reading V buffer
        if (kt + 1 < NT) load_v(kt + 1); // V(kt+1) hides behind next S + softmax
    }

    // normalize + write bf16 hi/lo
    #pragma unroll
    for (int r = 0; r < 2; r++) {
        float inv = 1.f / l2s[r];
        int row = t0 + 16 * w + g + 8 * r;
        #pragma unroll
        for (int nf = 0; nf < 8; nf++) {
            int col = h * HDD + nf * 8 + 2 * t;
            float v0 = o[nf][2 * r] * inv;
            float v1 = o[nf][2 * r + 1] * inv;
            __nv_bfloat16 h0, l0, h1, l1;
            bf16split(v0, h0, l0);
            bf16split(v1, h1, l1);
            size_t idx = (size_t)(b * TT + row) * DD + col;
            *reinterpret_cast<unsigned*>(&outH[idx]) = pack2(h0, h1);
            *reinterpret_cast<unsigned*>(&outL[idx]) = pack2(l0, l1);
        }
    }
}

// ---------------------------------------------------------------------------
extern "C" void kernel_launch(void* const* d_in, const int* in_sizes, int n_in,
                              void* d_out, int out_size)
{
    const float* x     = (const float*)d_in[0];
    const float* w_qkv = (const float*)d_in[1];
    const float* b_qkv = (const float*)d_in[2];
    const float* w_out = (const float*)d_in[3];
    const float* b_out = (const float*)d_in[4];
    float* out = (float*)d_out;

    __nv_bfloat16 *xh, *xl, *wqh, *wql, *woh, *wol, *qkvh, *qkvl, *ah, *al;
    cudaGetSymbolAddress((void**)&xh,   g_xh);
    cudaGetSymbolAddress((void**)&xl,   g_xl);
    cudaGetSymbolAddress((void**)&wqh,  g_wqkvT_h);
    cudaGetSymbolAddress((void**)&wql,  g_wqkvT_l);
    cudaGetSymbolAddress((void**)&woh,  g_woutT_h);
    cudaGetSymbolAddress((void**)&wol,  g_woutT_l);
    cudaGetSymbolAddress((void**)&qkvh, g_qkvH);
    cudaGetSymbolAddress((void**)&qkvl, g_qkvL);
    cudaGetSymbolAddress((void**)&ah,   g_attnH);
    cudaGetSymbolAddress((void**)&al,   g_attnL);

    const int GEMM_SMEM = 3 * 32768;   // 96 KB, 3-stage
    cudaFuncSetAttribute(gemm_mma_kernel,
                         cudaFuncAttributeMaxDynamicSharedMemorySize, GEMM_SMEM);
    const int ATTN_SMEM = 6 * 8192;    // 48 KB
    cudaFuncSetAttribute(attn_tc_kernel,
                         cudaFuncAttributeMaxDynamicSharedMemorySize, ATTN_SMEM);

    // Pre-pass: split X; transpose+split weights
    {
        int n4 = BB * TT * DD / 4;
        split_kernel<<<(n4 + 255) / 256, 256>>>(x, xh, xl, n4);
        dim3 bt(32, 8);
        transpose_split_kernel<<<dim3(3 * DD / 32, DD / 32), bt>>>(w_qkv, wqh, wql, DD, 3 * DD);
        transpose_split_kernel<<<dim3(DD / 32, DD / 32), bt>>>(w_out, woh, wol, DD, DD);
    }

    // 1) QKV projection -> bf16 hi/lo (Q pre-scaled by 0.125)
    gemm_mma_kernel<<<dim3(3 * DD / 128, BB * TT / 128), 256, GEMM_SMEM>>>(
        xh, xl, wqh, wql, b_qkv, nullptr, qkvh, qkvl, 3 * DD, DD, 1);

    // 2) Attention -> bf16 hi/lo
    attn_tc_kernel<<<dim3(TT / 64, HH, BB), 128, ATTN_SMEM>>>(qkvh, qkvl, ah, al);

    // 3) Output projection -> fp32 d_out
    gemm_mma_kernel<<<dim3(DD / 128, BB * TT / 128), 256, GEMM_SMEM>>>(
        ah, al, woh, wol, b_out, out, nullptr, nullptr, DD, DD, 0);
}